// round 9
// baseline (speedup 1.0000x reference)
#include <cuda_runtime.h>
#include <cuda_fp16.h>
#include <cstdint>
#include <cstddef>

// Problem constants: B=16384, ND=20, D_G=D_H=64, D_EMB=16, pred_len=12.
#define MAXB 16384
#define ND 20
#define BPB 32          // batch elements per block (4 per warp, 8 warps)
#define FULLM 0xffffffffu

typedef unsigned long long ull;

// Time-invariant precompute scratch (fp16). ~52 MB total -> mostly L2-resident.
__device__ __half g_preh[(size_t)ND * MAXB * 64];  // [n][b][k]  pre = inter@Wc1[:64]+bc1
__device__ __half g_igh [(size_t)ND * MAXB * 16];  // [n][b][j]  ig  = inter@We[:64]

__device__ __forceinline__ float tanh_hw(float x) {
    float y; asm("tanh.approx.f32 %0, %1;" : "=f"(y) : "f"(x)); return y;
}
__device__ __forceinline__ float sig_hw(float x) {
    return fmaf(tanh_hw(0.5f * x), 0.5f, 0.5f);
}
__device__ __forceinline__ ull pack2(float v) {
    ull r; asm("mov.b64 %0, {%1, %1};" : "=l"(r) : "f"(v)); return r;
}
__device__ __forceinline__ float2 unpack2(ull u) {
    float2 v; asm("mov.b64 {%0, %1}, %2;" : "=f"(v.x), "=f"(v.y) : "l"(u)); return v;
}

// ---------------------------------------------------------------------------
// Precompute (one pass over intermediate):
//   pre[m][0:64] = A[m] @ Wc1[:64]  + bc1   (fp16)
//   ig [m][0:16] = A[m] @ We[:64]           (fp16)
// ---------------------------------------------------------------------------
__global__ void precomp_kernel(const float* __restrict__ A,
                               const float* __restrict__ Wc1,
                               const float* __restrict__ bc1,
                               const float* __restrict__ We)
{
    __shared__ float As[64][68];
    __shared__ float Ws[64][80];

    const int tid = threadIdx.x;
    const int m0  = blockIdx.x * 64;

    const float4* Ag = reinterpret_cast<const float4*>(A + (size_t)m0 * 64);
    #pragma unroll
    for (int i = 0; i < 8; i++) {
        int idx = tid + i * 128;
        int r = idx >> 4, k4 = (idx & 15) << 2;
        float4 v = Ag[idx];
        As[k4 + 0][r] = v.x; As[k4 + 1][r] = v.y;
        As[k4 + 2][r] = v.z; As[k4 + 3][r] = v.w;
    }
    for (int i = tid; i < 64 * 80; i += 128) {
        int k = i / 80, c = i - k * 80;
        Ws[k][c] = (c < 64) ? Wc1[k * 64 + c] : We[k * 16 + (c - 64)];
    }
    __syncthreads();

    const int tx = tid & 15;
    const int ty = tid >> 4;

    float acc[8][5];
    #pragma unroll
    for (int i = 0; i < 8; i++)
        #pragma unroll
        for (int j = 0; j < 5; j++) acc[i][j] = 0.f;

    #pragma unroll 4
    for (int k = 0; k < 64; k++) {
        float wv[5];
        #pragma unroll
        for (int j = 0; j < 5; j++) wv[j] = Ws[k][tx + 16 * j];
        float4 a0 = *reinterpret_cast<const float4*>(&As[k][ty << 3]);
        float4 a1 = *reinterpret_cast<const float4*>(&As[k][(ty << 3) + 4]);
        float av[8] = {a0.x, a0.y, a0.z, a0.w, a1.x, a1.y, a1.z, a1.w};
        #pragma unroll
        for (int i = 0; i < 8; i++)
            #pragma unroll
            for (int j = 0; j < 5; j++)
                acc[i][j] = fmaf(av[i], wv[j], acc[i][j]);
    }

    #pragma unroll
    for (int j = 0; j < 5; j++) {
        int c = tx + 16 * j;
        float bv = (c < 64) ? bc1[c] : 0.f;
        #pragma unroll
        for (int i = 0; i < 8; i++) {
            int r = m0 + (ty << 3) + i;
            float v = acc[i][j] + bv;
            if (c < 64) g_preh[(size_t)r * 64 + c]        = __float2half_rn(v);
            else        g_igh [(size_t)r * 16 + (c - 64)] = __float2half_rn(v);
        }
    }
}

// ---------------------------------------------------------------------------
// Fused persistent step kernel. Each WARP owns 4 batch rows end-to-end.
// sW / sWihp stored column-PERMUTED so each lane's 8 (resp. 6) needed columns
// are contiguous -> LDS.128 loads.
// ---------------------------------------------------------------------------
// smem layout (float offsets):
#define SW_OFF     0          // [64][256] permuted combined W   16384
#define SWIHP_OFF  16384      // [16][32][8] permuted Wih         4096
#define SH_OFF     20480      // [32][68]  h (16B-aligned rows)   2176
#define SBIH_OFF   22656      // [192] bih
#define SBHH_OFF   22848      // [192] bhh
#define SWO_OFF    23040      // [128] Wo
#define SWC2_OFF   23168      // [64]  Wc2
#define SWEY_OFF   23232      // [32]  We rows 64,65
#define SBE_OFF    23264      // [16]  be
#define SBO_OFF    23280      // [2]   bo
#define SMEM_FLOATS 23282
#define SMEM_BYTES  (SMEM_FLOATS * 4)

__global__ void __launch_bounds__(256, 2)
step_kernel(const float* __restrict__ lastx,
            const float* __restrict__ zo,
            const float* __restrict__ Wc1,
            const float* __restrict__ Whh,
            const float* __restrict__ bhh,
            const float* __restrict__ Wih,
            const float* __restrict__ bih,
            const float* __restrict__ Wc2,
            const float* __restrict__ We,
            const float* __restrict__ be,
            const float* __restrict__ Wo,
            const float* __restrict__ bo,
            float* __restrict__ out,
            int B, int pred_len)
{
    extern __shared__ float sm[];
    float* sW    = sm + SW_OFF;
    float* sWihp = sm + SWIHP_OFF;
    float* sh    = sm + SH_OFF;
    float* sbih  = sm + SBIH_OFF;
    float* sbhh  = sm + SBHH_OFF;
    float* sWo   = sm + SWO_OFF;
    float* sWc2  = sm + SWC2_OFF;
    float* sWeY  = sm + SWEY_OFF;
    float* sbe   = sm + SBE_OFF;
    float* sbo   = sm + SBO_OFF;

    const int tid  = threadIdx.x;
    const int lane = tid & 31;
    const int wrp  = tid >> 5;
    const int b0   = blockIdx.x * BPB;

    // ---- init: permuted weights + h ----
    for (int i = tid; i < 64 * 256; i += 256) {
        int k = i >> 8, p = i & 255;
        int l = p >> 3, q = p & 7;
        int c = ((q >> 1) << 6) + 2 * l + (q & 1);   // {hp,r,z,n} pairs per lane
        sW[i] = (c < 64) ? Wc1[(64 + k) * 64 + c] : Whh[k * 192 + (c - 64)];
    }
    for (int i = tid; i < 16 * 256; i += 256) {
        int k = i >> 8, p = i & 255;
        int l = p >> 3, q = p & 7;
        float v = 0.f;
        if (q < 6) v = Wih[k * 192 + ((q >> 1) << 6) + 2 * l + (q & 1)];
        sWihp[i] = v;
    }
    if (tid < 192) { sbih[tid] = bih[tid]; sbhh[tid] = bhh[tid]; }
    if (tid < 128) sWo[tid]  = Wo[tid];
    if (tid < 64)  sWc2[tid] = Wc2[tid];
    if (tid < 32)  sWeY[tid] = We[64 * 16 + tid];
    if (tid < 16)  sbe[tid]  = be[tid];
    if (tid < 2)   sbo[tid]  = bo[tid];
    for (int i = tid; i < BPB * 64; i += 256) {
        int r = i >> 6, k = i & 63;
        sh[r * 68 + k] = zo[(size_t)(b0 + r) * 64 + k];
    }
    __syncthreads();

    // ---- hoisted per-lane constants ----
    const int   c2  = 2 * lane;
    const float wA  = sWc2[c2];
    const float wB  = sWc2[c2 + 1];
    const float wo0 = sWo[lane * 2],        wo1 = sWo[lane * 2 + 1];
    const float wo2 = sWo[(lane + 32) * 2], wo3 = sWo[(lane + 32) * 2 + 1];
    const float bo0 = sbo[0], bo1 = sbo[1];
    const float cR0 = sbih[c2]       + sbhh[c2];         // bih+bhh folded (r,z)
    const float cR1 = sbih[c2 + 1]   + sbhh[c2 + 1];
    const float cZ0 = sbih[64 + c2]  + sbhh[64 + c2];
    const float cZ1 = sbih[64 + c2 + 1] + sbhh[64 + c2 + 1];
    const float biN0 = sbih[128 + c2],  biN1 = sbih[128 + c2 + 1];
    const float bhN0 = sbhh[128 + c2],  bhN1 = sbhh[128 + c2 + 1];
    const int   lane16 = lane & 15;                       // OOB-safe ig lane
    const float weY0 = sWeY[lane16];
    const float weY1 = sWeY[16 + lane16];
    const float bev  = sbe[lane16];
    const bool  hi16 = (lane & 16) != 0;

    const __half2* preh2 = reinterpret_cast<const __half2*>(g_preh);
    const size_t preStride = (size_t)B * 32;     // half2 units per dest
    const size_t igStride  = (size_t)B * 16;     // half units per dest

    for (int t = 0; t < pred_len; t++) {
        // ============ Phase A: acc2 = h(4 rows) @ Wperm ============
        ull acc2[4][4];
        #pragma unroll
        for (int i = 0; i < 4; i++)
            #pragma unroll
            for (int j = 0; j < 4; j++) acc2[i][j] = 0ull;

        #pragma unroll
        for (int k4 = 0; k4 < 16; k4++) {
            float4 h4[4];
            #pragma unroll
            for (int i = 0; i < 4; i++)
                h4[i] = *reinterpret_cast<const float4*>(
                    &sh[(4 * wrp + i) * 68 + 4 * k4]);
            #pragma unroll
            for (int kk = 0; kk < 4; kk++) {
                const float* wp = &sW[(4 * k4 + kk) * 256 + lane * 8];
                ulonglong2 w01 = *reinterpret_cast<const ulonglong2*>(wp);
                ulonglong2 w23 = *reinterpret_cast<const ulonglong2*>(wp + 4);
                #pragma unroll
                for (int i = 0; i < 4; i++) {
                    float hv = (kk == 0) ? h4[i].x : (kk == 1) ? h4[i].y
                             : (kk == 2) ? h4[i].z : h4[i].w;
                    ull h2 = pack2(hv);
                    asm("fma.rn.f32x2 %0, %1, %2, %0;" : "+l"(acc2[i][0]) : "l"(h2), "l"(w01.x));
                    asm("fma.rn.f32x2 %0, %1, %2, %0;" : "+l"(acc2[i][1]) : "l"(h2), "l"(w01.y));
                    asm("fma.rn.f32x2 %0, %1, %2, %0;" : "+l"(acc2[i][2]) : "l"(h2), "l"(w23.x));
                    asm("fma.rn.f32x2 %0, %1, %2, %0;" : "+l"(acc2[i][3]) : "l"(h2), "l"(w23.y));
                }
            }
        }

        // ============ Phases B+C per owned row ============
        #pragma unroll 1
        for (int i = 0; i < 4; i++) {
            const int bl = 4 * wrp + i;
            const int bg = b0 + bl;

            // ---- y = h @ Wo + bo (paired reduce: s0 in lanes<16, s1 in >=16) --
            float y0, y1;
            if (t == 0) {
                y0 = lastx[2 * bg];
                y1 = lastx[2 * bg + 1];
            } else {
                float h0 = sh[bl * 68 + lane];
                float h1 = sh[bl * 68 + 32 + lane];
                float s0 = h0 * wo0 + h1 * wo2;
                float s1 = h0 * wo1 + h1 * wo3;
                float x  = hi16 ? s1 : s0;
                float ys = hi16 ? s0 : s1;
                float v  = x + __shfl_xor_sync(FULLM, ys, 16);
                v += __shfl_xor_sync(FULLM, v, 8);
                v += __shfl_xor_sync(FULLM, v, 4);
                v += __shfl_xor_sync(FULLM, v, 2);
                v += __shfl_xor_sync(FULLM, v, 1);
                float w = __shfl_xor_sync(FULLM, v, 16);
                y0 = (hi16 ? w : v) + bo0;
                y1 = (hi16 ? v : w) + bo1;
                if (lane == 0) {
                    float2 yo = make_float2(y0, y1);
                    *reinterpret_cast<float2*>(
                        &out[((size_t)(t - 1) * B + bg) * 2]) = yo;
                }
            }

            // ---- attention scores (dest pairs, exact paired butterfly) ----
            const float2 hp = unpack2(acc2[i][0]);
            const __half2* pp = preh2 + (size_t)bg * 32 + lane;
            float cn[ND];
            #pragma unroll
            for (int n = 0; n < ND; n += 2) {
                float2 p0 = __half22float2(pp[0]);
                float2 p1 = __half22float2(pp[preStride]);
                pp += 2 * preStride;
                float pa = tanh_hw(p0.x + hp.x) * wA + tanh_hw(p0.y + hp.y) * wB;
                float pb = tanh_hw(p1.x + hp.x) * wA + tanh_hw(p1.y + hp.y) * wB;
                float x  = hi16 ? pb : pa;
                float ys = hi16 ? pa : pb;
                float v  = x + __shfl_xor_sync(FULLM, ys, 16);
                v += __shfl_xor_sync(FULLM, v, 8);
                v += __shfl_xor_sync(FULLM, v, 4);
                v += __shfl_xor_sync(FULLM, v, 2);
                v += __shfl_xor_sync(FULLM, v, 1);
                float w = __shfl_xor_sync(FULLM, v, 16);
                cn[n]     = hi16 ? w : v;
                cn[n + 1] = hi16 ? v : w;
            }

            // ---- softmax over 20 dests (no max-sub: |c| <= ~5, safe) ----
            float s = 0.f;
            #pragma unroll
            for (int n = 0; n < ND; n++) { cn[n] = __expf(cn[n]); s += cn[n]; }
            const float inv = 1.f / s;

            // ---- weighted ig + embedding (lane<16 holds emb[lane];
            //      lanes>=16 compute a duplicate with lane&15 -> no OOB) ----
            float embv;
            {
                const __half* ip = g_igh + (size_t)bg * 16 + lane16;
                float wa = 0.f;
                #pragma unroll
                for (int n = 0; n < ND; n++) {
                    wa = fmaf(cn[n], __half2float(*ip), wa);
                    ip += igStride;
                }
                wa *= inv;
                embv = wa + y0 * weY0 + y1 * weY1 + bev;
            }

            // ---- GRU: gi = emb @ Wih (permuted LDS.128), gates from acc2 ----
            ull aR = 0ull, aZ = 0ull, aN = 0ull;
            #pragma unroll
            for (int k = 0; k < 16; k++) {
                float e = __shfl_sync(FULLM, embv, k);
                ull e2 = pack2(e);
                const float* wp = &sWihp[k * 256 + lane * 8];
                ulonglong2 wrz = *reinterpret_cast<const ulonglong2*>(wp);
                ull wnn = *reinterpret_cast<const ull*>(wp + 4);
                asm("fma.rn.f32x2 %0, %1, %2, %0;" : "+l"(aR) : "l"(e2), "l"(wrz.x));
                asm("fma.rn.f32x2 %0, %1, %2, %0;" : "+l"(aZ) : "l"(e2), "l"(wrz.y));
                asm("fma.rn.f32x2 %0, %1, %2, %0;" : "+l"(aN) : "l"(e2), "l"(wnn));
            }
            float2 gR = unpack2(aR), gZ = unpack2(aZ), gN = unpack2(aN);
            float2 hR = unpack2(acc2[i][1]);
            float2 hZ = unpack2(acc2[i][2]);
            float2 hN = unpack2(acc2[i][3]);

            float r0 = sig_hw(gR.x + hR.x + cR0);
            float r1 = sig_hw(gR.y + hR.y + cR1);
            float z0 = sig_hw(gZ.x + hZ.x + cZ0);
            float z1 = sig_hw(gZ.y + hZ.y + cZ1);
            float n0 = tanh_hw(gN.x + biN0 + r0 * (hN.x + bhN0));
            float n1 = tanh_hw(gN.y + biN1 + r1 * (hN.y + bhN1));

            float ho0 = sh[bl * 68 + c2];
            float ho1 = sh[bl * 68 + c2 + 1];
            __syncwarp();
            sh[bl * 68 + c2]     = fmaf(z0, ho0 - n0, n0);
            sh[bl * 68 + c2 + 1] = fmaf(z1, ho1 - n1, n1);
        }
        __syncwarp();
    }

    // ---- final output row: ys[pred_len-1] = h @ Wo + bo ----
    #pragma unroll 1
    for (int i = 0; i < 4; i++) {
        const int bl = 4 * wrp + i;
        const int bg = b0 + bl;
        float h0 = sh[bl * 68 + lane];
        float h1 = sh[bl * 68 + 32 + lane];
        float s0 = h0 * wo0 + h1 * wo2;
        float s1 = h0 * wo1 + h1 * wo3;
        float x  = hi16 ? s1 : s0;
        float ys = hi16 ? s0 : s1;
        float v  = x + __shfl_xor_sync(FULLM, ys, 16);
        v += __shfl_xor_sync(FULLM, v, 8);
        v += __shfl_xor_sync(FULLM, v, 4);
        v += __shfl_xor_sync(FULLM, v, 2);
        v += __shfl_xor_sync(FULLM, v, 1);
        float w = __shfl_xor_sync(FULLM, v, 16);
        if (lane == 0) {
            float2 yo = make_float2(v + bo0, w + bo1);
            *reinterpret_cast<float2*>(
                &out[((size_t)(pred_len - 1) * B + bg) * 2]) = yo;
        }
    }
}

// ---------------------------------------------------------------------------
// Host launcher: 2 kernels total.
// ---------------------------------------------------------------------------
extern "C" void kernel_launch(void* const* d_in, const int* in_sizes, int n_in,
                              void* d_out, int out_size)
{
    const int o = (in_sizes[0] == 1) ? 1 : 0;

    const float* lastx = (const float*)d_in[o + 0];
    const float* zo    = (const float*)d_in[o + 1];
    const float* inter = (const float*)d_in[o + 3];
    const float* We    = (const float*)d_in[o + 4];
    const float* be    = (const float*)d_in[o + 5];
    const float* Wih   = (const float*)d_in[o + 6];
    const float* Whh   = (const float*)d_in[o + 7];
    const float* bih   = (const float*)d_in[o + 8];
    const float* bhh   = (const float*)d_in[o + 9];
    const float* Wc1   = (const float*)d_in[o + 10];
    const float* bc1   = (const float*)d_in[o + 11];
    const float* Wc2   = (const float*)d_in[o + 12];
    const float* Wo    = (const float*)d_in[o + 14];
    const float* bo    = (const float*)d_in[o + 15];
    float* out = (float*)d_out;

    const int B = in_sizes[o + 0] / 2;
    const int pred_len = out_size / (2 * B);
    (void)n_in;

    static bool attr_done = false;
    if (!attr_done) {
        cudaFuncSetAttribute(step_kernel,
                             cudaFuncAttributeMaxDynamicSharedMemorySize,
                             SMEM_BYTES);
        attr_done = true;
    }

    precomp_kernel<<<(ND * B) / 64, 128>>>(inter, Wc1, bc1, We);

    step_kernel<<<B / BPB, 256, SMEM_BYTES>>>(lastx, zo, Wc1, Whh, bhh,
                                              Wih, bih, Wc2, We, be, Wo, bo,
                                              out, B, pred_len);
}

// round 10
// speedup vs baseline: 1.4740x; 1.4740x over previous
#include <cuda_runtime.h>
#include <cuda_fp16.h>
#include <cstdint>
#include <cstddef>

// Problem constants: B=16384, ND=20, D_G=D_H=64, D_EMB=16, pred_len=12.
#define MAXB 16384
#define ND 20
#define BPB 32          // batch elements per block (4 per warp, 8 warps)
#define FULLM 0xffffffffu

typedef unsigned long long ull;

// Time-invariant precompute scratch (fp16). ~52 MB total -> mostly L2-resident.
__device__ __half g_preh[(size_t)ND * MAXB * 64];  // [n][b][k]  pre = inter@Wc1[:64]+bc1
__device__ __half g_igh [(size_t)ND * MAXB * 16];  // [n][b][j]  ig  = inter@We[:64]

__device__ __forceinline__ float tanh_hw(float x) {
    float y; asm("tanh.approx.f32 %0, %1;" : "=f"(y) : "f"(x)); return y;
}
__device__ __forceinline__ float ex2_hw(float x) {
    float y; asm("ex2.approx.f32 %0, %1;" : "=f"(y) : "f"(x)); return y;
}
__device__ __forceinline__ ull pack2(float v) {
    ull r; asm("mov.b64 %0, {%1, %1};" : "=l"(r) : "f"(v)); return r;
}
__device__ __forceinline__ float2 unpack2(ull u) {
    float2 v; asm("mov.b64 {%0, %1}, %2;" : "=f"(v.x), "=f"(v.y) : "l"(u)); return v;
}

// ---------------------------------------------------------------------------
// Precompute (one pass over intermediate):
//   pre[m][0:64] = A[m] @ Wc1[:64]  + bc1   (fp16)
//   ig [m][0:16] = A[m] @ We[:64]           (fp16)
// ---------------------------------------------------------------------------
__global__ void precomp_kernel(const float* __restrict__ A,
                               const float* __restrict__ Wc1,
                               const float* __restrict__ bc1,
                               const float* __restrict__ We)
{
    __shared__ float As[64][68];
    __shared__ float Ws[64][80];

    const int tid = threadIdx.x;
    const int m0  = blockIdx.x * 64;

    const float4* Ag = reinterpret_cast<const float4*>(A + (size_t)m0 * 64);
    #pragma unroll
    for (int i = 0; i < 8; i++) {
        int idx = tid + i * 128;
        int r = idx >> 4, k4 = (idx & 15) << 2;
        float4 v = Ag[idx];
        As[k4 + 0][r] = v.x; As[k4 + 1][r] = v.y;
        As[k4 + 2][r] = v.z; As[k4 + 3][r] = v.w;
    }
    for (int i = tid; i < 64 * 80; i += 128) {
        int k = i / 80, c = i - k * 80;
        Ws[k][c] = (c < 64) ? Wc1[k * 64 + c] : We[k * 16 + (c - 64)];
    }
    __syncthreads();

    const int tx = tid & 15;
    const int ty = tid >> 4;

    float acc[8][5];
    #pragma unroll
    for (int i = 0; i < 8; i++)
        #pragma unroll
        for (int j = 0; j < 5; j++) acc[i][j] = 0.f;

    #pragma unroll 4
    for (int k = 0; k < 64; k++) {
        float wv[5];
        #pragma unroll
        for (int j = 0; j < 5; j++) wv[j] = Ws[k][tx + 16 * j];
        float4 a0 = *reinterpret_cast<const float4*>(&As[k][ty << 3]);
        float4 a1 = *reinterpret_cast<const float4*>(&As[k][(ty << 3) + 4]);
        float av[8] = {a0.x, a0.y, a0.z, a0.w, a1.x, a1.y, a1.z, a1.w};
        #pragma unroll
        for (int i = 0; i < 8; i++)
            #pragma unroll
            for (int j = 0; j < 5; j++)
                acc[i][j] = fmaf(av[i], wv[j], acc[i][j]);
    }

    #pragma unroll
    for (int j = 0; j < 5; j++) {
        int c = tx + 16 * j;
        float bv = (c < 64) ? bc1[c] : 0.f;
        #pragma unroll
        for (int i = 0; i < 8; i++) {
            int r = m0 + (ty << 3) + i;
            float v = acc[i][j] + bv;
            if (c < 64) g_preh[(size_t)r * 64 + c]        = __float2half_rn(v);
            else        g_igh [(size_t)r * 16 + (c - 64)] = __float2half_rn(v);
        }
    }
}

// ---------------------------------------------------------------------------
// Fused persistent step kernel. Each WARP owns 4 batch rows end-to-end.
// R5 memory layout (LDS.64 wv pattern), plus: float4 broadcast h-loads,
// online softmax (no cn[] array), paired exact butterflies, HW sigmoid
// with 0.5 folded into r/z weights, log2e folded into Wc2.
// ---------------------------------------------------------------------------
// smem layout (float offsets):
#define SW_OFF     0          // [64][256] combined W (r/z cols pre-scaled 0.5)
#define SWIH_OFF   16384      // [16][192] Wih (r/z cols pre-scaled 0.5)
#define SH_OFF     19456      // [32][68]  h (16B-aligned rows)   2176
#define SBIH_OFF   21632      // [192] bih
#define SBHH_OFF   21824      // [192] bhh
#define SWO_OFF    22016      // [128] Wo
#define SWC2_OFF   22144      // [64]  Wc2
#define SWEY_OFF   22208      // [32]  We rows 64,65
#define SBE_OFF    22240      // [16]  be
#define SBO_OFF    22256      // [2]   bo
#define SMEM_FLOATS 22258
#define SMEM_BYTES  (SMEM_FLOATS * 4)

__global__ void __launch_bounds__(256, 2)
step_kernel(const float* __restrict__ lastx,
            const float* __restrict__ zo,
            const float* __restrict__ Wc1,
            const float* __restrict__ Whh,
            const float* __restrict__ bhh,
            const float* __restrict__ Wih,
            const float* __restrict__ bih,
            const float* __restrict__ Wc2,
            const float* __restrict__ We,
            const float* __restrict__ be,
            const float* __restrict__ Wo,
            const float* __restrict__ bo,
            float* __restrict__ out,
            int B, int pred_len)
{
    extern __shared__ float sm[];
    float* sW   = sm + SW_OFF;
    float* sWih = sm + SWIH_OFF;
    float* sh   = sm + SH_OFF;
    float* sbih = sm + SBIH_OFF;
    float* sbhh = sm + SBHH_OFF;
    float* sWo  = sm + SWO_OFF;
    float* sWc2 = sm + SWC2_OFF;
    float* sWeY = sm + SWEY_OFF;
    float* sbe  = sm + SBE_OFF;
    float* sbo  = sm + SBO_OFF;

    const int tid  = threadIdx.x;
    const int lane = tid & 31;
    const int wrp  = tid >> 5;
    const int b0   = blockIdx.x * BPB;

    // ---- init: weights (r/z blocks pre-scaled by 0.5 for HW sigmoid) + h ----
    for (int i = tid; i < 64 * 256; i += 256) {
        int k = i >> 8, c = i & 255;
        float v = (c < 64) ? Wc1[(64 + k) * 64 + c] : Whh[k * 192 + (c - 64)];
        if (c >= 64 && c < 192) v *= 0.5f;      // r,z gate columns
        sW[i] = v;
    }
    for (int i = tid; i < 16 * 192; i += 256) {
        int c = i % 192;
        float v = Wih[i];
        if (c < 128) v *= 0.5f;                 // r,z gate columns
        sWih[i] = v;
    }
    if (tid < 192) { sbih[tid] = bih[tid]; sbhh[tid] = bhh[tid]; }
    if (tid < 128) sWo[tid]  = Wo[tid];
    if (tid < 64)  sWc2[tid] = Wc2[tid];
    if (tid < 32)  sWeY[tid] = We[64 * 16 + tid];
    if (tid < 16)  sbe[tid]  = be[tid];
    if (tid < 2)   sbo[tid]  = bo[tid];
    for (int i = tid; i < BPB * 64; i += 256) {
        int r = i >> 6, k = i & 63;
        sh[r * 68 + k] = zo[(size_t)(b0 + r) * 64 + k];
    }
    __syncthreads();

    // ---- hoisted per-lane constants ----
    const int   c2  = 2 * lane;
    const float LOG2E = 1.4426950408889634f;
    const float wA  = sWc2[c2] * LOG2E;          // log2e folded -> bare ex2
    const float wB  = sWc2[c2 + 1] * LOG2E;
    const float wo0 = sWo[lane * 2],        wo1 = sWo[lane * 2 + 1];
    const float wo2 = sWo[(lane + 32) * 2], wo3 = sWo[(lane + 32) * 2 + 1];
    const float bo0 = sbo[0], bo1 = sbo[1];
    const float cR0 = 0.5f * (sbih[c2]          + sbhh[c2]);
    const float cR1 = 0.5f * (sbih[c2 + 1]      + sbhh[c2 + 1]);
    const float cZ0 = 0.5f * (sbih[64 + c2]     + sbhh[64 + c2]);
    const float cZ1 = 0.5f * (sbih[64 + c2 + 1] + sbhh[64 + c2 + 1]);
    const float biN0 = sbih[128 + c2],  biN1 = sbih[128 + c2 + 1];
    const float bhN0 = sbhh[128 + c2],  bhN1 = sbhh[128 + c2 + 1];
    const int   lane16 = lane & 15;              // OOB-safe ig lane
    const float weY0 = sWeY[lane16];
    const float weY1 = sWeY[16 + lane16];
    const float bev  = sbe[lane16];
    const bool  hi16 = (lane & 16) != 0;

    const __half2* preh2 = reinterpret_cast<const __half2*>(g_preh);
    const size_t preStride = (size_t)B * 32;     // half2 units per dest
    const size_t igStride  = (size_t)B * 16;     // half units per dest

    for (int t = 0; t < pred_len; t++) {
        // ============ Phase A: acc2 = h(4 rows) @ [Wc1h | Whh'] ============
        ull acc2[4][4];
        #pragma unroll
        for (int i = 0; i < 4; i++)
            #pragma unroll
            for (int j = 0; j < 4; j++) acc2[i][j] = 0ull;

        #pragma unroll 2
        for (int k4 = 0; k4 < 16; k4++) {
            float4 h4[4];
            #pragma unroll
            for (int i = 0; i < 4; i++)
                h4[i] = *reinterpret_cast<const float4*>(
                    &sh[(4 * wrp + i) * 68 + 4 * k4]);
            #pragma unroll
            for (int kk = 0; kk < 4; kk++) {
                const float* wr = &sW[(4 * k4 + kk) * 256 + c2];
                ull wv0 = *reinterpret_cast<const ull*>(wr);
                ull wv1 = *reinterpret_cast<const ull*>(wr + 64);
                ull wv2 = *reinterpret_cast<const ull*>(wr + 128);
                ull wv3 = *reinterpret_cast<const ull*>(wr + 192);
                #pragma unroll
                for (int i = 0; i < 4; i++) {
                    float hv = (kk == 0) ? h4[i].x : (kk == 1) ? h4[i].y
                             : (kk == 2) ? h4[i].z : h4[i].w;
                    ull h2 = pack2(hv);
                    asm("fma.rn.f32x2 %0, %1, %2, %0;" : "+l"(acc2[i][0]) : "l"(h2), "l"(wv0));
                    asm("fma.rn.f32x2 %0, %1, %2, %0;" : "+l"(acc2[i][1]) : "l"(h2), "l"(wv1));
                    asm("fma.rn.f32x2 %0, %1, %2, %0;" : "+l"(acc2[i][2]) : "l"(h2), "l"(wv2));
                    asm("fma.rn.f32x2 %0, %1, %2, %0;" : "+l"(acc2[i][3]) : "l"(h2), "l"(wv3));
                }
            }
        }

        // ============ Phases B+C per owned row ============
        #pragma unroll 1
        for (int i = 0; i < 4; i++) {
            const int bl = 4 * wrp + i;
            const int bg = b0 + bl;

            // ---- y = h @ Wo + bo (paired exact butterfly) ----
            float y0, y1;
            if (t == 0) {
                y0 = lastx[2 * bg];
                y1 = lastx[2 * bg + 1];
            } else {
                float h0 = sh[bl * 68 + lane];
                float h1 = sh[bl * 68 + 32 + lane];
                float s0 = h0 * wo0 + h1 * wo2;
                float s1 = h0 * wo1 + h1 * wo3;
                float x  = hi16 ? s1 : s0;
                float ys = hi16 ? s0 : s1;
                float v  = x + __shfl_xor_sync(FULLM, ys, 16);
                v += __shfl_xor_sync(FULLM, v, 8);
                v += __shfl_xor_sync(FULLM, v, 4);
                v += __shfl_xor_sync(FULLM, v, 2);
                v += __shfl_xor_sync(FULLM, v, 1);
                float w = __shfl_xor_sync(FULLM, v, 16);
                y0 = (hi16 ? w : v) + bo0;
                y1 = (hi16 ? v : w) + bo1;
                if (lane == 0) {
                    float2 yo = make_float2(y0, y1);
                    *reinterpret_cast<float2*>(
                        &out[((size_t)(t - 1) * B + bg) * 2]) = yo;
                }
            }

            // ---- online attention: scores + exp + weighted-ig in one loop --
            const float2 hp = unpack2(acc2[i][0]);
            const __half2* pp = preh2 + (size_t)bg * 32 + lane;
            const __half*  ip = g_igh + (size_t)bg * 16 + lane16;
            float ssum = 0.f, wa = 0.f;
            #pragma unroll
            for (int n = 0; n < ND; n += 2) {
                float2 p0 = __half22float2(pp[0]);
                float2 p1 = __half22float2(pp[preStride]);
                pp += 2 * preStride;
                float pa = tanh_hw(p0.x + hp.x) * wA + tanh_hw(p0.y + hp.y) * wB;
                float pb = tanh_hw(p1.x + hp.x) * wA + tanh_hw(p1.y + hp.y) * wB;
                float x  = hi16 ? pb : pa;
                float ys = hi16 ? pa : pb;
                float v  = x + __shfl_xor_sync(FULLM, ys, 16);
                v += __shfl_xor_sync(FULLM, v, 8);
                v += __shfl_xor_sync(FULLM, v, 4);
                v += __shfl_xor_sync(FULLM, v, 2);
                v += __shfl_xor_sync(FULLM, v, 1);
                float w = __shfl_xor_sync(FULLM, v, 16);
                float e0 = ex2_hw(hi16 ? w : v);     // exp(compab[n])
                float e1 = ex2_hw(hi16 ? v : w);     // exp(compab[n+1])
                ssum += e0;
                ssum += e1;
                wa = fmaf(e0, __half2float(ip[0]), wa);
                wa = fmaf(e1, __half2float(ip[igStride]), wa);
                ip += 2 * igStride;
            }
            const float inv = 1.f / ssum;
            float embv = fmaf(wa, inv,
                              fmaf(y0, weY0, fmaf(y1, weY1, bev)));

            // ---- GRU: gi = emb @ Wih', gates from acc2[i][1..3] ----
            ull aR = 0ull, aZ = 0ull, aN = 0ull;
            #pragma unroll
            for (int k = 0; k < 16; k++) {
                float e = __shfl_sync(FULLM, embv, k);
                ull e2 = pack2(e);
                ull wr_ = *reinterpret_cast<const ull*>(&sWih[k * 192 + c2]);
                ull wz_ = *reinterpret_cast<const ull*>(&sWih[k * 192 + 64 + c2]);
                ull wn_ = *reinterpret_cast<const ull*>(&sWih[k * 192 + 128 + c2]);
                asm("fma.rn.f32x2 %0, %1, %2, %0;" : "+l"(aR) : "l"(e2), "l"(wr_));
                asm("fma.rn.f32x2 %0, %1, %2, %0;" : "+l"(aZ) : "l"(e2), "l"(wz_));
                asm("fma.rn.f32x2 %0, %1, %2, %0;" : "+l"(aN) : "l"(e2), "l"(wn_));
            }
            float2 gR = unpack2(aR), gZ = unpack2(aZ), gN = unpack2(aN);
            float2 hR = unpack2(acc2[i][1]);   // pre-scaled by 0.5
            float2 hZ = unpack2(acc2[i][2]);   // pre-scaled by 0.5
            float2 hN = unpack2(acc2[i][3]);

            // sigmoid(x) = 0.5*tanh(0.5x)+0.5 ; the 0.5x is prefolded
            float r0 = fmaf(tanh_hw(gR.x + hR.x + cR0), 0.5f, 0.5f);
            float r1 = fmaf(tanh_hw(gR.y + hR.y + cR1), 0.5f, 0.5f);
            float z0 = fmaf(tanh_hw(gZ.x + hZ.x + cZ0), 0.5f, 0.5f);
            float z1 = fmaf(tanh_hw(gZ.y + hZ.y + cZ1), 0.5f, 0.5f);
            float n0 = tanh_hw(gN.x + biN0 + r0 * (hN.x + bhN0));
            float n1 = tanh_hw(gN.y + biN1 + r1 * (hN.y + bhN1));

            float ho0 = sh[bl * 68 + c2];
            float ho1 = sh[bl * 68 + c2 + 1];
            __syncwarp();
            sh[bl * 68 + c2]     = fmaf(z0, ho0 - n0, n0);
            sh[bl * 68 + c2 + 1] = fmaf(z1, ho1 - n1, n1);
        }
        __syncwarp();
    }

    // ---- final output row: ys[pred_len-1] = h @ Wo + bo ----
    #pragma unroll 1
    for (int i = 0; i < 4; i++) {
        const int bl = 4 * wrp + i;
        const int bg = b0 + bl;
        float h0 = sh[bl * 68 + lane];
        float h1 = sh[bl * 68 + 32 + lane];
        float s0 = h0 * wo0 + h1 * wo2;
        float s1 = h0 * wo1 + h1 * wo3;
        float x  = hi16 ? s1 : s0;
        float ys = hi16 ? s0 : s1;
        float v  = x + __shfl_xor_sync(FULLM, ys, 16);
        v += __shfl_xor_sync(FULLM, v, 8);
        v += __shfl_xor_sync(FULLM, v, 4);
        v += __shfl_xor_sync(FULLM, v, 2);
        v += __shfl_xor_sync(FULLM, v, 1);
        float w = __shfl_xor_sync(FULLM, v, 16);
        if (lane == 0) {
            float2 yo = make_float2(v + bo0, w + bo1);
            *reinterpret_cast<float2*>(
                &out[((size_t)(pred_len - 1) * B + bg) * 2]) = yo;
        }
    }
}

// ---------------------------------------------------------------------------
// Host launcher: 2 kernels total.
// ---------------------------------------------------------------------------
extern "C" void kernel_launch(void* const* d_in, const int* in_sizes, int n_in,
                              void* d_out, int out_size)
{
    const int o = (in_sizes[0] == 1) ? 1 : 0;

    const float* lastx = (const float*)d_in[o + 0];
    const float* zo    = (const float*)d_in[o + 1];
    const float* inter = (const float*)d_in[o + 3];
    const float* We    = (const float*)d_in[o + 4];
    const float* be    = (const float*)d_in[o + 5];
    const float* Wih   = (const float*)d_in[o + 6];
    const float* Whh   = (const float*)d_in[o + 7];
    const float* bih   = (const float*)d_in[o + 8];
    const float* bhh   = (const float*)d_in[o + 9];
    const float* Wc1   = (const float*)d_in[o + 10];
    const float* bc1   = (const float*)d_in[o + 11];
    const float* Wc2   = (const float*)d_in[o + 12];
    const float* Wo    = (const float*)d_in[o + 14];
    const float* bo    = (const float*)d_in[o + 15];
    float* out = (float*)d_out;

    const int B = in_sizes[o + 0] / 2;
    const int pred_len = out_size / (2 * B);
    (void)n_in;

    static bool attr_done = false;
    if (!attr_done) {
        cudaFuncSetAttribute(step_kernel,
                             cudaFuncAttributeMaxDynamicSharedMemorySize,
                             SMEM_BYTES);
        attr_done = true;
    }

    precomp_kernel<<<(ND * B) / 64, 128>>>(inter, Wc1, bc1, We);

    step_kernel<<<B / BPB, 256, SMEM_BYTES>>>(lastx, zo, Wc1, Whh, bhh,
                                              Wih, bih, Wc2, We, be, Wo, bo,
                                              out, B, pred_len);
}

// round 11
// speedup vs baseline: 1.4871x; 1.0089x over previous
#include <cuda_runtime.h>
#include <cuda_fp16.h>
#include <cstdint>
#include <cstddef>

// Problem constants: B=16384, ND=20, D_G=D_H=64, D_EMB=16, pred_len=12.
#define MAXB 16384
#define ND 20
#define BPB 32          // batch elements per block (4 per warp, 8 warps)
#define FULLM 0xffffffffu

typedef unsigned long long ull;

// Time-invariant precompute scratch (fp16). ~52 MB total -> mostly L2-resident.
__device__ __half g_preh[(size_t)ND * MAXB * 64];  // [n][b][k]  pre = inter@Wc1[:64]+bc1
__device__ __half g_igh [(size_t)ND * MAXB * 16];  // [n][b][j]  ig  = inter@We[:64]

__device__ __forceinline__ float tanh_hw(float x) {
    float y; asm("tanh.approx.f32 %0, %1;" : "=f"(y) : "f"(x)); return y;
}
__device__ __forceinline__ float ex2_hw(float x) {
    float y; asm("ex2.approx.f32 %0, %1;" : "=f"(y) : "f"(x)); return y;
}
__device__ __forceinline__ ull pack2(float v) {
    ull r; asm("mov.b64 %0, {%1, %1};" : "=l"(r) : "f"(v)); return r;
}
__device__ __forceinline__ float2 unpack2(ull u) {
    float2 v; asm("mov.b64 {%0, %1}, %2;" : "=f"(v.x), "=f"(v.y) : "l"(u)); return v;
}
// half2 (as uint) -> f32x2 packed in a 64-bit reg
__device__ __forceinline__ ull cvt_h2_ull(unsigned int h) {
    __half2 hh = *reinterpret_cast<__half2*>(&h);
    float2 f = __half22float2(hh);
    ull r; asm("mov.b64 %0, {%1, %2};" : "=l"(r) : "f"(f.x), "f"(f.y));
    return r;
}
__device__ __forceinline__ unsigned int packh2(float a, float b) {
    __half2 hh = __floats2half2_rn(a, b);
    return *reinterpret_cast<unsigned int*>(&hh);
}

// ---------------------------------------------------------------------------
// Precompute (one pass over intermediate):
//   pre[m][0:64] = A[m] @ Wc1[:64]  + bc1   (fp16)
//   ig [m][0:16] = A[m] @ We[:64]           (fp16)
// ---------------------------------------------------------------------------
__global__ void precomp_kernel(const float* __restrict__ A,
                               const float* __restrict__ Wc1,
                               const float* __restrict__ bc1,
                               const float* __restrict__ We)
{
    __shared__ float As[64][68];
    __shared__ float Ws[64][80];

    const int tid = threadIdx.x;
    const int m0  = blockIdx.x * 64;

    const float4* Ag = reinterpret_cast<const float4*>(A + (size_t)m0 * 64);
    #pragma unroll
    for (int i = 0; i < 8; i++) {
        int idx = tid + i * 128;
        int r = idx >> 4, k4 = (idx & 15) << 2;
        float4 v = Ag[idx];
        As[k4 + 0][r] = v.x; As[k4 + 1][r] = v.y;
        As[k4 + 2][r] = v.z; As[k4 + 3][r] = v.w;
    }
    for (int i = tid; i < 64 * 80; i += 128) {
        int k = i / 80, c = i - k * 80;
        Ws[k][c] = (c < 64) ? Wc1[k * 64 + c] : We[k * 16 + (c - 64)];
    }
    __syncthreads();

    const int tx = tid & 15;
    const int ty = tid >> 4;

    float acc[8][5];
    #pragma unroll
    for (int i = 0; i < 8; i++)
        #pragma unroll
        for (int j = 0; j < 5; j++) acc[i][j] = 0.f;

    #pragma unroll 4
    for (int k = 0; k < 64; k++) {
        float wv[5];
        #pragma unroll
        for (int j = 0; j < 5; j++) wv[j] = Ws[k][tx + 16 * j];
        float4 a0 = *reinterpret_cast<const float4*>(&As[k][ty << 3]);
        float4 a1 = *reinterpret_cast<const float4*>(&As[k][(ty << 3) + 4]);
        float av[8] = {a0.x, a0.y, a0.z, a0.w, a1.x, a1.y, a1.z, a1.w};
        #pragma unroll
        for (int i = 0; i < 8; i++)
            #pragma unroll
            for (int j = 0; j < 5; j++)
                acc[i][j] = fmaf(av[i], wv[j], acc[i][j]);
    }

    #pragma unroll
    for (int j = 0; j < 5; j++) {
        int c = tx + 16 * j;
        float bv = (c < 64) ? bc1[c] : 0.f;
        #pragma unroll
        for (int i = 0; i < 8; i++) {
            int r = m0 + (ty << 3) + i;
            float v = acc[i][j] + bv;
            if (c < 64) g_preh[(size_t)r * 64 + c]        = __float2half_rn(v);
            else        g_igh [(size_t)r * 16 + (c - 64)] = __float2half_rn(v);
        }
    }
}

// ---------------------------------------------------------------------------
// Fused persistent step kernel. Each WARP owns 4 batch rows end-to-end.
// Phase A weights fp16-packed, lane-permuted: one LDS.128 per k serves all
// 4 gate blocks (columns 2l,2l+1 each). Wih likewise, shared across row pairs.
// ---------------------------------------------------------------------------
// smem layout (float offsets):
#define SWH_OFF    0          // [64][32] uint4 fp16 packed W   8192 floats (32KB)
#define SWIHH_OFF  8192       // [16][32] uint4 fp16 packed Wih 2048 floats (8KB)
#define SH_OFF     10240      // [32][68] h                     2176
#define SBIH_OFF   12416      // [192] bih
#define SBHH_OFF   12608      // [192] bhh
#define SWO_OFF    12800      // [128] Wo
#define SWC2_OFF   12928      // [64]  Wc2
#define SWEY_OFF   12992      // [32]  We rows 64,65
#define SBE_OFF    13024      // [16]  be
#define SBO_OFF    13040      // [2]   bo
#define SMEM_FLOATS 13042
#define SMEM_BYTES  (SMEM_FLOATS * 4)

__global__ void __launch_bounds__(256, 2)
step_kernel(const float* __restrict__ lastx,
            const float* __restrict__ zo,
            const float* __restrict__ Wc1,
            const float* __restrict__ Whh,
            const float* __restrict__ bhh,
            const float* __restrict__ Wih,
            const float* __restrict__ bih,
            const float* __restrict__ Wc2,
            const float* __restrict__ We,
            const float* __restrict__ be,
            const float* __restrict__ Wo,
            const float* __restrict__ bo,
            float* __restrict__ out,
            int B, int pred_len)
{
    extern __shared__ float sm[];
    uint4* sWh   = reinterpret_cast<uint4*>(sm + SWH_OFF);    // [64*32]
    uint4* sWihh = reinterpret_cast<uint4*>(sm + SWIHH_OFF);  // [16*32]
    float* sh    = sm + SH_OFF;
    float* sbih  = sm + SBIH_OFF;
    float* sbhh  = sm + SBHH_OFF;
    float* sWo   = sm + SWO_OFF;
    float* sWc2  = sm + SWC2_OFF;
    float* sWeY  = sm + SWEY_OFF;
    float* sbe   = sm + SBE_OFF;
    float* sbo   = sm + SBO_OFF;

    const int tid  = threadIdx.x;
    const int lane = tid & 31;
    const int wrp  = tid >> 5;
    const int b0   = blockIdx.x * BPB;

    // ---- init: fp16-packed lane-permuted weights + h ----
    for (int i = tid; i < 64 * 32; i += 256) {
        int k = i >> 5, l = i & 31, c = 2 * l;
        uint4 u;
        u.x = packh2(Wc1[(64 + k) * 64 + c],        Wc1[(64 + k) * 64 + c + 1]);
        u.y = packh2(0.5f * Whh[k * 192 + c],       0.5f * Whh[k * 192 + c + 1]);
        u.z = packh2(0.5f * Whh[k * 192 + 64 + c],  0.5f * Whh[k * 192 + 64 + c + 1]);
        u.w = packh2(Whh[k * 192 + 128 + c],        Whh[k * 192 + 128 + c + 1]);
        sWh[i] = u;
    }
    for (int i = tid; i < 16 * 32; i += 256) {
        int k = i >> 5, l = i & 31, c = 2 * l;
        uint4 u;
        u.x = packh2(0.5f * Wih[k * 192 + c],       0.5f * Wih[k * 192 + c + 1]);
        u.y = packh2(0.5f * Wih[k * 192 + 64 + c],  0.5f * Wih[k * 192 + 64 + c + 1]);
        u.z = packh2(Wih[k * 192 + 128 + c],        Wih[k * 192 + 128 + c + 1]);
        u.w = 0;
        sWihh[i] = u;
    }
    if (tid < 192) { sbih[tid] = bih[tid]; sbhh[tid] = bhh[tid]; }
    if (tid < 128) sWo[tid]  = Wo[tid];
    if (tid < 64)  sWc2[tid] = Wc2[tid];
    if (tid < 32)  sWeY[tid] = We[64 * 16 + tid];
    if (tid < 16)  sbe[tid]  = be[tid];
    if (tid < 2)   sbo[tid]  = bo[tid];
    for (int i = tid; i < BPB * 64; i += 256) {
        int r = i >> 6, k = i & 63;
        sh[r * 68 + k] = zo[(size_t)(b0 + r) * 64 + k];
    }
    __syncthreads();

    // ---- hoisted per-lane constants ----
    const int   c2  = 2 * lane;
    const float LOG2E = 1.4426950408889634f;
    const float wA  = sWc2[c2] * LOG2E;          // log2e folded -> bare ex2
    const float wB  = sWc2[c2 + 1] * LOG2E;
    const float wo0 = sWo[lane * 2],        wo1 = sWo[lane * 2 + 1];
    const float wo2 = sWo[(lane + 32) * 2], wo3 = sWo[(lane + 32) * 2 + 1];
    const float bo0 = sbo[0], bo1 = sbo[1];
    const float cR0 = 0.5f * (sbih[c2]          + sbhh[c2]);
    const float cR1 = 0.5f * (sbih[c2 + 1]      + sbhh[c2 + 1]);
    const float cZ0 = 0.5f * (sbih[64 + c2]     + sbhh[64 + c2]);
    const float cZ1 = 0.5f * (sbih[64 + c2 + 1] + sbhh[64 + c2 + 1]);
    const float biN0 = sbih[128 + c2],  biN1 = sbih[128 + c2 + 1];
    const float bhN0 = sbhh[128 + c2],  bhN1 = sbhh[128 + c2 + 1];
    const int   lane16 = lane & 15;              // OOB-safe ig lane
    const float weY0 = sWeY[lane16];
    const float weY1 = sWeY[16 + lane16];
    const float bev  = sbe[lane16];
    const bool  hi16 = (lane & 16) != 0;

    const __half2* preh2 = reinterpret_cast<const __half2*>(g_preh);
    const size_t preStride = (size_t)B * 32;     // half2 units per dest
    const size_t igStride  = (size_t)B * 16;     // half units per dest

    for (int t = 0; t < pred_len; t++) {
        // ============ Phase A: acc2 = h(4 rows) @ [hp|r'|z'|n] fp16 weights ==
        ull acc2[4][4];
        #pragma unroll
        for (int i = 0; i < 4; i++)
            #pragma unroll
            for (int j = 0; j < 4; j++) acc2[i][j] = 0ull;

        #pragma unroll 2
        for (int k4 = 0; k4 < 16; k4++) {
            float4 h4[4];
            #pragma unroll
            for (int i = 0; i < 4; i++)
                h4[i] = *reinterpret_cast<const float4*>(
                    &sh[(4 * wrp + i) * 68 + 4 * k4]);
            #pragma unroll
            for (int kk = 0; kk < 4; kk++) {
                uint4 wp = sWh[(4 * k4 + kk) * 32 + lane];
                ull wv0 = cvt_h2_ull(wp.x);
                ull wv1 = cvt_h2_ull(wp.y);
                ull wv2 = cvt_h2_ull(wp.z);
                ull wv3 = cvt_h2_ull(wp.w);
                #pragma unroll
                for (int i = 0; i < 4; i++) {
                    float hv = (kk == 0) ? h4[i].x : (kk == 1) ? h4[i].y
                             : (kk == 2) ? h4[i].z : h4[i].w;
                    ull h2 = pack2(hv);
                    asm("fma.rn.f32x2 %0, %1, %2, %0;" : "+l"(acc2[i][0]) : "l"(h2), "l"(wv0));
                    asm("fma.rn.f32x2 %0, %1, %2, %0;" : "+l"(acc2[i][1]) : "l"(h2), "l"(wv1));
                    asm("fma.rn.f32x2 %0, %1, %2, %0;" : "+l"(acc2[i][2]) : "l"(h2), "l"(wv2));
                    asm("fma.rn.f32x2 %0, %1, %2, %0;" : "+l"(acc2[i][3]) : "l"(h2), "l"(wv3));
                }
            }
        }

        // ============ Phase B: y + online attention per row -> embv[i] ======
        float embv[4];
        #pragma unroll 1
        for (int i = 0; i < 4; i++) {
            const int bl = 4 * wrp + i;
            const int bg = b0 + bl;

            float y0, y1;
            if (t == 0) {
                y0 = lastx[2 * bg];
                y1 = lastx[2 * bg + 1];
            } else {
                float h0 = sh[bl * 68 + lane];
                float h1 = sh[bl * 68 + 32 + lane];
                float s0 = h0 * wo0 + h1 * wo2;
                float s1 = h0 * wo1 + h1 * wo3;
                float x  = hi16 ? s1 : s0;
                float ys = hi16 ? s0 : s1;
                float v  = x + __shfl_xor_sync(FULLM, ys, 16);
                v += __shfl_xor_sync(FULLM, v, 8);
                v += __shfl_xor_sync(FULLM, v, 4);
                v += __shfl_xor_sync(FULLM, v, 2);
                v += __shfl_xor_sync(FULLM, v, 1);
                float w = __shfl_xor_sync(FULLM, v, 16);
                y0 = (hi16 ? w : v) + bo0;
                y1 = (hi16 ? v : w) + bo1;
                if (lane == 0) {
                    float2 yo = make_float2(y0, y1);
                    *reinterpret_cast<float2*>(
                        &out[((size_t)(t - 1) * B + bg) * 2]) = yo;
                }
            }

            const float2 hp = unpack2(acc2[i][0]);
            const __half2* pp = preh2 + (size_t)bg * 32 + lane;
            const __half*  ip = g_igh + (size_t)bg * 16 + lane16;
            float ssum = 0.f, wa = 0.f;
            #pragma unroll
            for (int n = 0; n < ND; n += 2) {
                float2 p0 = __half22float2(pp[0]);
                float2 p1 = __half22float2(pp[preStride]);
                pp += 2 * preStride;
                float pa = tanh_hw(p0.x + hp.x) * wA + tanh_hw(p0.y + hp.y) * wB;
                float pb = tanh_hw(p1.x + hp.x) * wA + tanh_hw(p1.y + hp.y) * wB;
                float x  = hi16 ? pb : pa;
                float ys = hi16 ? pa : pb;
                float v  = x + __shfl_xor_sync(FULLM, ys, 16);
                v += __shfl_xor_sync(FULLM, v, 8);
                v += __shfl_xor_sync(FULLM, v, 4);
                v += __shfl_xor_sync(FULLM, v, 2);
                v += __shfl_xor_sync(FULLM, v, 1);
                float w = __shfl_xor_sync(FULLM, v, 16);
                float e0 = ex2_hw(hi16 ? w : v);
                float e1 = ex2_hw(hi16 ? v : w);
                ssum += e0;
                ssum += e1;
                wa = fmaf(e0, __half2float(ip[0]), wa);
                wa = fmaf(e1, __half2float(ip[igStride]), wa);
                ip += 2 * igStride;
            }
            const float inv = 1.f / ssum;
            embv[i] = fmaf(wa, inv, fmaf(y0, weY0, fmaf(y1, weY1, bev)));
        }

        // ============ Phase C: GRU, Wih shared across row pairs ============
        #pragma unroll
        for (int p = 0; p < 2; p++) {
            ull aR0 = 0ull, aZ0 = 0ull, aN0 = 0ull;
            ull aR1 = 0ull, aZ1 = 0ull, aN1 = 0ull;
            #pragma unroll
            for (int k = 0; k < 16; k++) {
                uint4 wp = sWihh[k * 32 + lane];
                ull wr = cvt_h2_ull(wp.x);
                ull wz = cvt_h2_ull(wp.y);
                ull wn = cvt_h2_ull(wp.z);
                ull e20 = pack2(__shfl_sync(FULLM, embv[2 * p],     k));
                ull e21 = pack2(__shfl_sync(FULLM, embv[2 * p + 1], k));
                asm("fma.rn.f32x2 %0, %1, %2, %0;" : "+l"(aR0) : "l"(e20), "l"(wr));
                asm("fma.rn.f32x2 %0, %1, %2, %0;" : "+l"(aZ0) : "l"(e20), "l"(wz));
                asm("fma.rn.f32x2 %0, %1, %2, %0;" : "+l"(aN0) : "l"(e20), "l"(wn));
                asm("fma.rn.f32x2 %0, %1, %2, %0;" : "+l"(aR1) : "l"(e21), "l"(wr));
                asm("fma.rn.f32x2 %0, %1, %2, %0;" : "+l"(aZ1) : "l"(e21), "l"(wz));
                asm("fma.rn.f32x2 %0, %1, %2, %0;" : "+l"(aN1) : "l"(e21), "l"(wn));
            }
            #pragma unroll
            for (int q = 0; q < 2; q++) {
                const int i  = 2 * p + q;
                const int bl = 4 * wrp + i;
                float2 gR = unpack2(q == 0 ? aR0 : aR1);
                float2 gZ = unpack2(q == 0 ? aZ0 : aZ1);
                float2 gN = unpack2(q == 0 ? aN0 : aN1);
                float2 hR = unpack2(acc2[i][1]);   // pre-scaled by 0.5
                float2 hZ = unpack2(acc2[i][2]);   // pre-scaled by 0.5
                float2 hN = unpack2(acc2[i][3]);

                float r0 = fmaf(tanh_hw(gR.x + hR.x + cR0), 0.5f, 0.5f);
                float r1 = fmaf(tanh_hw(gR.y + hR.y + cR1), 0.5f, 0.5f);
                float z0 = fmaf(tanh_hw(gZ.x + hZ.x + cZ0), 0.5f, 0.5f);
                float z1 = fmaf(tanh_hw(gZ.y + hZ.y + cZ1), 0.5f, 0.5f);
                float n0 = tanh_hw(gN.x + biN0 + r0 * (hN.x + bhN0));
                float n1 = tanh_hw(gN.y + biN1 + r1 * (hN.y + bhN1));

                float ho0 = sh[bl * 68 + c2];
                float ho1 = sh[bl * 68 + c2 + 1];
                sh[bl * 68 + c2]     = fmaf(z0, ho0 - n0, n0);
                sh[bl * 68 + c2 + 1] = fmaf(z1, ho1 - n1, n1);
            }
        }
        __syncwarp();   // h fully updated before next step's reads
    }

    // ---- final output row: ys[pred_len-1] = h @ Wo + bo ----
    #pragma unroll 1
    for (int i = 0; i < 4; i++) {
        const int bl = 4 * wrp + i;
        const int bg = b0 + bl;
        float h0 = sh[bl * 68 + lane];
        float h1 = sh[bl * 68 + 32 + lane];
        float s0 = h0 * wo0 + h1 * wo2;
        float s1 = h0 * wo1 + h1 * wo3;
        float x  = hi16 ? s1 : s0;
        float ys = hi16 ? s0 : s1;
        float v  = x + __shfl_xor_sync(FULLM, ys, 16);
        v += __shfl_xor_sync(FULLM, v, 8);
        v += __shfl_xor_sync(FULLM, v, 4);
        v += __shfl_xor_sync(FULLM, v, 2);
        v += __shfl_xor_sync(FULLM, v, 1);
        float w = __shfl_xor_sync(FULLM, v, 16);
        if (lane == 0) {
            float2 yo = make_float2(v + bo0, w + bo1);
            *reinterpret_cast<float2*>(
                &out[((size_t)(pred_len - 1) * B + bg) * 2]) = yo;
        }
    }
}

// ---------------------------------------------------------------------------
// Host launcher: 2 kernels total.
// ---------------------------------------------------------------------------
extern "C" void kernel_launch(void* const* d_in, const int* in_sizes, int n_in,
                              void* d_out, int out_size)
{
    const int o = (in_sizes[0] == 1) ? 1 : 0;

    const float* lastx = (const float*)d_in[o + 0];
    const float* zo    = (const float*)d_in[o + 1];
    const float* inter = (const float*)d_in[o + 3];
    const float* We    = (const float*)d_in[o + 4];
    const float* be    = (const float*)d_in[o + 5];
    const float* Wih   = (const float*)d_in[o + 6];
    const float* Whh   = (const float*)d_in[o + 7];
    const float* bih   = (const float*)d_in[o + 8];
    const float* bhh   = (const float*)d_in[o + 9];
    const float* Wc1   = (const float*)d_in[o + 10];
    const float* bc1   = (const float*)d_in[o + 11];
    const float* Wc2   = (const float*)d_in[o + 12];
    const float* Wo    = (const float*)d_in[o + 14];
    const float* bo    = (const float*)d_in[o + 15];
    float* out = (float*)d_out;

    const int B = in_sizes[o + 0] / 2;
    const int pred_len = out_size / (2 * B);
    (void)n_in;

    static bool attr_done = false;
    if (!attr_done) {
        cudaFuncSetAttribute(step_kernel,
                             cudaFuncAttributeMaxDynamicSharedMemorySize,
                             SMEM_BYTES);
        attr_done = true;
    }

    precomp_kernel<<<(ND * B) / 64, 128>>>(inter, Wc1, bc1, We);

    step_kernel<<<B / BPB, 256, SMEM_BYTES>>>(lastx, zo, Wc1, Whh, bhh,
                                              Wih, bih, Wc2, We, be, Wo, bo,
                                              out, B, pred_len);
}

// round 13
// speedup vs baseline: 1.6313x; 1.0970x over previous
#include <cuda_runtime.h>
#include <cuda_fp16.h>
#include <cstdint>
#include <cstddef>

// Problem constants: B=16384, ND=20, D_G=D_H=64, D_EMB=16, pred_len=12.
#define MAXB 16384
#define ND 20
#define BPB 32          // batch elements per block (4 per warp, 8 warps)
#define FULLM 0xffffffffu

typedef unsigned long long ull;

// Time-invariant precompute scratch (fp16). ~52 MB total -> L2-resident.
__device__ __half g_preh[(size_t)ND * MAXB * 64];  // [n][b][k]  pre = inter@Wc1[:64]+bc1
__device__ __half g_igh [(size_t)ND * MAXB * 16];  // [n][b][j]  ig  = inter@We[:64]

__device__ __forceinline__ float tanh_hw(float x) {
    float y; asm("tanh.approx.f32 %0, %1;" : "=f"(y) : "f"(x)); return y;
}
__device__ __forceinline__ float ex2_hw(float x) {
    float y; asm("ex2.approx.f32 %0, %1;" : "=f"(y) : "f"(x)); return y;
}
__device__ __forceinline__ ull pack2(float v) {
    ull r; asm("mov.b64 %0, {%1, %1};" : "=l"(r) : "f"(v)); return r;
}
__device__ __forceinline__ float2 unpack2(ull u) {
    float2 v; asm("mov.b64 {%0, %1}, %2;" : "=f"(v.x), "=f"(v.y) : "l"(u)); return v;
}
__device__ __forceinline__ ull cvt_h2_ull(unsigned int h) {
    __half2 hh = *reinterpret_cast<__half2*>(&h);
    float2 f = __half22float2(hh);
    ull r; asm("mov.b64 %0, {%1, %2};" : "=l"(r) : "f"(f.x), "f"(f.y));
    return r;
}
__device__ __forceinline__ unsigned int packh2(float a, float b) {
    __half2 hh = __floats2half2_rn(a, b);
    return *reinterpret_cast<unsigned int*>(&hh);
}

// ---------------------------------------------------------------------------
// Precompute (one pass over intermediate).
// ---------------------------------------------------------------------------
__global__ void precomp_kernel(const float* __restrict__ A,
                               const float* __restrict__ Wc1,
                               const float* __restrict__ bc1,
                               const float* __restrict__ We)
{
    __shared__ float As[64][68];
    __shared__ float Ws[64][80];

    const int tid = threadIdx.x;
    const int m0  = blockIdx.x * 64;

    const float4* Ag = reinterpret_cast<const float4*>(A + (size_t)m0 * 64);
    #pragma unroll
    for (int i = 0; i < 8; i++) {
        int idx = tid + i * 128;
        int r = idx >> 4, k4 = (idx & 15) << 2;
        float4 v = Ag[idx];
        As[k4 + 0][r] = v.x; As[k4 + 1][r] = v.y;
        As[k4 + 2][r] = v.z; As[k4 + 3][r] = v.w;
    }
    for (int i = tid; i < 64 * 80; i += 128) {
        int k = i / 80, c = i - k * 80;
        Ws[k][c] = (c < 64) ? Wc1[k * 64 + c] : We[k * 16 + (c - 64)];
    }
    __syncthreads();

    const int tx = tid & 15;
    const int ty = tid >> 4;

    float acc[8][5];
    #pragma unroll
    for (int i = 0; i < 8; i++)
        #pragma unroll
        for (int j = 0; j < 5; j++) acc[i][j] = 0.f;

    #pragma unroll 4
    for (int k = 0; k < 64; k++) {
        float wv[5];
        #pragma unroll
        for (int j = 0; j < 5; j++) wv[j] = Ws[k][tx + 16 * j];
        float4 a0 = *reinterpret_cast<const float4*>(&As[k][ty << 3]);
        float4 a1 = *reinterpret_cast<const float4*>(&As[k][(ty << 3) + 4]);
        float av[8] = {a0.x, a0.y, a0.z, a0.w, a1.x, a1.y, a1.z, a1.w};
        #pragma unroll
        for (int i = 0; i < 8; i++)
            #pragma unroll
            for (int j = 0; j < 5; j++)
                acc[i][j] = fmaf(av[i], wv[j], acc[i][j]);
    }

    #pragma unroll
    for (int j = 0; j < 5; j++) {
        int c = tx + 16 * j;
        float bv = (c < 64) ? bc1[c] : 0.f;
        #pragma unroll
        for (int i = 0; i < 8; i++) {
            int r = m0 + (ty << 3) + i;
            float v = acc[i][j] + bv;
            if (c < 64) g_preh[(size_t)r * 64 + c]        = __float2half_rn(v);
            else        g_igh [(size_t)r * 16 + (c - 64)] = __float2half_rn(v);
        }
    }
}

// ---------------------------------------------------------------------------
// smem byte offsets (all 16B aligned where needed)
// sW2 : fp16 [64][280]  combined W cols: 0-63 hp, 64-127 r*.5, 128-191 z*.5,
//                        192-255 n, 256-257 Wo, 258-271 zero  (35840 B)
// sHh : fp16 [32][72]   h copy for mma A                      ( 4608 B)
// sG  : f32  [32][280]  GEMM result (hp|r|z|n|y)              (35840 B)
// ---------------------------------------------------------------------------
#define OFF_W2    0
#define OFF_HH    35840
#define OFF_G     40448
#define OFF_WIHH  76288      // uint4 fp16 packed Wih [16][32]   8192 B
#define OFF_HF    84480      // f32 [32][68] h                   8704 B
#define OFF_BIH   93184
#define OFF_BHH   93952
#define OFF_WO    94720
#define OFF_WC2   95232
#define OFF_WEY   95488
#define OFF_BE    95616
#define OFF_BO    95680
#define SMEM_BYTES 95688

#define W2_STRIDE_B 560      // 280 halfs
#define HH_STRIDE_B 144      // 72 halfs
#define G_STRIDE    280      // f32

__device__ __forceinline__ uint32_t smem_u32(const void* p) {
    return (uint32_t)__cvta_generic_to_shared(p);
}

#define LDMX4(r0,r1,r2,r3,addr) \
    asm volatile("ldmatrix.sync.aligned.m8n8.x4.shared.b16 {%0,%1,%2,%3}, [%4];" \
        : "=r"(r0),"=r"(r1),"=r"(r2),"=r"(r3) : "r"(addr))
#define LDMX4T(r0,r1,r2,r3,addr) \
    asm volatile("ldmatrix.sync.aligned.m8n8.x4.trans.shared.b16 {%0,%1,%2,%3}, [%4];" \
        : "=r"(r0),"=r"(r1),"=r"(r2),"=r"(r3) : "r"(addr))
#define LDMX2T(r0,r1,addr) \
    asm volatile("ldmatrix.sync.aligned.m8n8.x2.trans.shared.b16 {%0,%1}, [%2];" \
        : "=r"(r0),"=r"(r1) : "r"(addr))
#define MMA16816(d0,d1,d2,d3,a0,a1,a2,a3,b0,b1) \
    asm volatile("mma.sync.aligned.m16n8k16.row.col.f32.f16.f16.f32 " \
        "{%0,%1,%2,%3}, {%4,%5,%6,%7}, {%8,%9}, {%0,%1,%2,%3};" \
        : "+f"(d0),"+f"(d1),"+f"(d2),"+f"(d3) \
        : "r"(a0),"r"(a1),"r"(a2),"r"(a3),"r"(b0),"r"(b1))

__global__ void __launch_bounds__(256, 2)
step_kernel(const float* __restrict__ lastx,
            const float* __restrict__ zo,
            const float* __restrict__ Wc1,
            const float* __restrict__ Whh,
            const float* __restrict__ bhh,
            const float* __restrict__ Wih,
            const float* __restrict__ bih,
            const float* __restrict__ Wc2,
            const float* __restrict__ We,
            const float* __restrict__ be,
            const float* __restrict__ Wo,
            const float* __restrict__ bo,
            float* __restrict__ out,
            int B, int pred_len)
{
    extern __shared__ char smc[];
    __half* sW2h  = reinterpret_cast<__half*>(smc + OFF_W2);
    __half* sHh   = reinterpret_cast<__half*>(smc + OFF_HH);
    float*  sG    = reinterpret_cast<float*>(smc + OFF_G);
    uint4*  sWihh = reinterpret_cast<uint4*>(smc + OFF_WIHH);
    float*  shf   = reinterpret_cast<float*>(smc + OFF_HF);
    float*  sbih  = reinterpret_cast<float*>(smc + OFF_BIH);
    float*  sbhh  = reinterpret_cast<float*>(smc + OFF_BHH);
    float*  sWo   = reinterpret_cast<float*>(smc + OFF_WO);
    float*  sWc2  = reinterpret_cast<float*>(smc + OFF_WC2);
    float*  sWeY  = reinterpret_cast<float*>(smc + OFF_WEY);
    float*  sbe   = reinterpret_cast<float*>(smc + OFF_BE);
    float*  sbo   = reinterpret_cast<float*>(smc + OFF_BO);

    const int tid  = threadIdx.x;
    const int lane = tid & 31;
    const int wrp  = tid >> 5;
    const int b0   = blockIdx.x * BPB;

    // ---- init weights ----
    for (int i = tid; i < 64 * 272; i += 256) {
        int k = i / 272, c = i - k * 272;
        float v;
        if      (c < 64)  v = Wc1[(64 + k) * 64 + c];
        else if (c < 128) v = 0.5f * Whh[k * 192 + (c - 64)];
        else if (c < 192) v = 0.5f * Whh[k * 192 + 64 + (c - 128)];
        else if (c < 256) v = Whh[k * 192 + 128 + (c - 192)];
        else if (c == 256) v = Wo[k * 2];
        else if (c == 257) v = Wo[k * 2 + 1];
        else v = 0.f;
        sW2h[k * 280 + c] = __float2half(v);
    }
    // zero the pad columns 272-279 too
    for (int i = tid; i < 64 * 8; i += 256) {
        int k = i >> 3, c = 272 + (i & 7);
        sW2h[k * 280 + c] = __float2half(0.f);
    }
    for (int i = tid; i < 16 * 32; i += 256) {
        int k = i >> 5, l = i & 31, c = 2 * l;
        uint4 u;
        u.x = packh2(0.5f * Wih[k * 192 + c],      0.5f * Wih[k * 192 + c + 1]);
        u.y = packh2(0.5f * Wih[k * 192 + 64 + c], 0.5f * Wih[k * 192 + 64 + c + 1]);
        u.z = packh2(Wih[k * 192 + 128 + c],       Wih[k * 192 + 128 + c + 1]);
        u.w = 0;
        sWihh[i] = u;
    }
    if (tid < 192) { sbih[tid] = bih[tid]; sbhh[tid] = bhh[tid]; }
    if (tid < 128) sWo[tid]  = Wo[tid];
    if (tid < 64)  sWc2[tid] = Wc2[tid];
    if (tid < 32)  sWeY[tid] = We[64 * 16 + tid];
    if (tid < 16)  sbe[tid]  = be[tid];
    if (tid < 2)   sbo[tid]  = bo[tid];
    for (int i = tid; i < BPB * 64; i += 256) {
        int r = i >> 6, k = i & 63;
        float v = zo[(size_t)(b0 + r) * 64 + k];
        shf[r * 68 + k] = v;
        sHh[r * 72 + k] = __float2half(v);
    }
    // zero fp16 h pad columns 64-71 (read by ldmatrix? no — k<=63; safe anyway)
    for (int i = tid; i < BPB * 8; i += 256) {
        int r = i >> 3, k = 64 + (i & 7);
        sHh[r * 72 + k] = __float2half(0.f);
    }
    __syncthreads();

    // ---- hoisted per-lane constants ----
    const int   c2  = 2 * lane;
    const float LOG2E = 1.4426950408889634f;
    const float wA  = sWc2[c2] * LOG2E;
    const float wB  = sWc2[c2 + 1] * LOG2E;
    const float wo0 = sWo[lane * 2],        wo1 = sWo[lane * 2 + 1];
    const float wo2 = sWo[(lane + 32) * 2], wo3 = sWo[(lane + 32) * 2 + 1];
    const float bo0 = sbo[0], bo1 = sbo[1];
    const float cR0 = 0.5f * (sbih[c2]          + sbhh[c2]);
    const float cR1 = 0.5f * (sbih[c2 + 1]      + sbhh[c2 + 1]);
    const float cZ0 = 0.5f * (sbih[64 + c2]     + sbhh[64 + c2]);
    const float cZ1 = 0.5f * (sbih[64 + c2 + 1] + sbhh[64 + c2 + 1]);
    const float biN0 = sbih[128 + c2],  biN1 = sbih[128 + c2 + 1];
    const float bhN0 = sbhh[128 + c2],  bhN1 = sbhh[128 + c2 + 1];
    const int   lane16 = lane & 15;
    const float weY0 = sWeY[lane16];
    const float weY1 = sWeY[16 + lane16];
    const float bev  = sbe[lane16];
    const bool  hi16 = (lane & 16) != 0;

    // ---- mma addressing (per-lane, hoisted) ----
    const int mb = 16 * (wrp & 1);          // m-tile rows
    const int nb = 64 * (wrp >> 1);         // n-range base
    const int sub = lane >> 3, srw = lane & 7;
    const uint32_t hhBase = smem_u32(sHh);
    const uint32_t w2Base = smem_u32(sW2h);
    // A: row = mb + srw + 8*(sub&1); k halfcol = 8*(sub>>1) (+16 per kt)
    const uint32_t aAddr0 = hhBase + (uint32_t)((mb + srw + 8 * (sub & 1)) * HH_STRIDE_B
                                                + (8 * (sub >> 1)) * 2);
    // B: krow = srw + 8*(sub&1) (+16 per kt); ncol = nb + 8*(sub>>1) (+16 per ng)
    const uint32_t bAddr0 = w2Base + (uint32_t)((srw + 8 * (sub & 1)) * W2_STRIDE_B
                                                + (nb + 8 * (sub >> 1)) * 2);
    // y-tile B (n8 at col 256); x2 uses addresses from lanes 0-15:
    //   mat0 = k rows 0-7, mat1 = k rows 8-15 (per kt)
    const uint32_t yAddr0 = w2Base + (uint32_t)(((lane & 7) + 8 * ((lane >> 3) & 1)) * W2_STRIDE_B
                                                + 256 * 2);

    const __half2* preh2 = reinterpret_cast<const __half2*>(g_preh);
    const size_t preStride = (size_t)B * 32;
    const size_t igStride  = (size_t)B * 16;

    for (int t = 0; t < pred_len; t++) {
        // ============ Phase A: tensor-core GEMM  sG = h_fp16 @ W_fp16 =======
        {
            float d[8][4];
            #pragma unroll
            for (int j = 0; j < 8; j++)
                #pragma unroll
                for (int q = 0; q < 4; q++) d[j][q] = 0.f;
            float e[4] = {0.f, 0.f, 0.f, 0.f};

            #pragma unroll
            for (int kt = 0; kt < 4; kt++) {
                uint32_t a0, a1, a2, a3;
                LDMX4(a0, a1, a2, a3, aAddr0 + kt * 32);
                uint32_t bb = bAddr0 + kt * (16 * W2_STRIDE_B);
                #pragma unroll
                for (int ng = 0; ng < 4; ng++) {
                    uint32_t q0, q1, q2, q3;
                    LDMX4T(q0, q1, q2, q3, bb + ng * 32);
                    MMA16816(d[2*ng][0], d[2*ng][1], d[2*ng][2], d[2*ng][3],
                             a0, a1, a2, a3, q0, q1);
                    MMA16816(d[2*ng+1][0], d[2*ng+1][1], d[2*ng+1][2], d[2*ng+1][3],
                             a0, a1, a2, a3, q2, q3);
                }
                if (wrp < 2) {
                    uint32_t y0r, y1r;
                    LDMX2T(y0r, y1r, yAddr0 + kt * (16 * W2_STRIDE_B));
                    MMA16816(e[0], e[1], e[2], e[3], a0, a1, a2, a3, y0r, y1r);
                }
            }
            // store D fragments
            const int gr = mb + (lane >> 2);
            const int gc = nb + 2 * (lane & 3);
            #pragma unroll
            for (int j = 0; j < 8; j++) {
                int col = gc + 8 * j;
                *reinterpret_cast<float2*>(&sG[gr * G_STRIDE + col]) =
                    make_float2(d[j][0], d[j][1]);
                *reinterpret_cast<float2*>(&sG[(gr + 8) * G_STRIDE + col]) =
                    make_float2(d[j][2], d[j][3]);
            }
            if (wrp < 2) {
                int col = 256 + 2 * (lane & 3);
                *reinterpret_cast<float2*>(&sG[gr * G_STRIDE + col]) =
                    make_float2(e[0], e[1]);
                *reinterpret_cast<float2*>(&sG[(gr + 8) * G_STRIDE + col]) =
                    make_float2(e[2], e[3]);
            }
        }
        __syncthreads();

        // ============ Phase B: y + online attention per row -> embv[i] ======
        float embv[4];
        #pragma unroll 1
        for (int i = 0; i < 4; i++) {
            const int bl = 4 * wrp + i;
            const int bg = b0 + bl;

            float y0, y1;
            if (t == 0) {
                y0 = lastx[2 * bg];
                y1 = lastx[2 * bg + 1];
            } else {
                float2 yv = *reinterpret_cast<const float2*>(&sG[bl * G_STRIDE + 256]);
                y0 = yv.x + bo0;
                y1 = yv.y + bo1;
                if (lane == 0) {
                    *reinterpret_cast<float2*>(
                        &out[((size_t)(t - 1) * B + bg) * 2]) = make_float2(y0, y1);
                }
            }

            const float2 hp = *reinterpret_cast<const float2*>(&sG[bl * G_STRIDE + c2]);
            const __half2* pp = preh2 + (size_t)bg * 32 + lane;
            const __half*  ip = g_igh + (size_t)bg * 16 + lane16;
            float ssum = 0.f, wa = 0.f;
            #pragma unroll
            for (int n = 0; n < ND; n += 2) {
                float2 p0 = __half22float2(pp[0]);
                float2 p1 = __half22float2(pp[preStride]);
                pp += 2 * preStride;
                float pa = tanh_hw(p0.x + hp.x) * wA + tanh_hw(p0.y + hp.y) * wB;
                float pb = tanh_hw(p1.x + hp.x) * wA + tanh_hw(p1.y + hp.y) * wB;
                float x  = hi16 ? pb : pa;
                float ys = hi16 ? pa : pb;
                float v  = x + __shfl_xor_sync(FULLM, ys, 16);
                v += __shfl_xor_sync(FULLM, v, 8);
                v += __shfl_xor_sync(FULLM, v, 4);
                v += __shfl_xor_sync(FULLM, v, 2);
                v += __shfl_xor_sync(FULLM, v, 1);
                float w = __shfl_xor_sync(FULLM, v, 16);
                float e0 = ex2_hw(hi16 ? w : v);
                float e1 = ex2_hw(hi16 ? v : w);
                ssum += e0;
                ssum += e1;
                wa = fmaf(e0, __half2float(ip[0]), wa);
                wa = fmaf(e1, __half2float(ip[igStride]), wa);
                ip += 2 * igStride;
            }
            const float inv = 1.f / ssum;
            embv[i] = fmaf(wa, inv, fmaf(y0, weY0, fmaf(y1, weY1, bev)));
        }

        // ============ Phase C: GRU, Wih shared across row pairs ============
        #pragma unroll
        for (int p = 0; p < 2; p++) {
            ull aR0 = 0ull, aZ0 = 0ull, aN0 = 0ull;
            ull aR1 = 0ull, aZ1 = 0ull, aN1 = 0ull;
            #pragma unroll
            for (int k = 0; k < 16; k++) {
                uint4 wp = sWihh[k * 32 + lane];
                ull wr = cvt_h2_ull(wp.x);
                ull wz = cvt_h2_ull(wp.y);
                ull wn = cvt_h2_ull(wp.z);
                ull e20 = pack2(__shfl_sync(FULLM, embv[2 * p],     k));
                ull e21 = pack2(__shfl_sync(FULLM, embv[2 * p + 1], k));
                asm("fma.rn.f32x2 %0, %1, %2, %0;" : "+l"(aR0) : "l"(e20), "l"(wr));
                asm("fma.rn.f32x2 %0, %1, %2, %0;" : "+l"(aZ0) : "l"(e20), "l"(wz));
                asm("fma.rn.f32x2 %0, %1, %2, %0;" : "+l"(aN0) : "l"(e20), "l"(wn));
                asm("fma.rn.f32x2 %0, %1, %2, %0;" : "+l"(aR1) : "l"(e21), "l"(wr));
                asm("fma.rn.f32x2 %0, %1, %2, %0;" : "+l"(aZ1) : "l"(e21), "l"(wz));
                asm("fma.rn.f32x2 %0, %1, %2, %0;" : "+l"(aN1) : "l"(e21), "l"(wn));
            }
            #pragma unroll
            for (int q = 0; q < 2; q++) {
                const int i  = 2 * p + q;
                const int bl = 4 * wrp + i;
                float2 gR = unpack2(q == 0 ? aR0 : aR1);
                float2 gZ = unpack2(q == 0 ? aZ0 : aZ1);
                float2 gN = unpack2(q == 0 ? aN0 : aN1);
                float2 hR = *reinterpret_cast<const float2*>(&sG[bl * G_STRIDE + 64 + c2]);
                float2 hZ = *reinterpret_cast<const float2*>(&sG[bl * G_STRIDE + 128 + c2]);
                float2 hN = *reinterpret_cast<const float2*>(&sG[bl * G_STRIDE + 192 + c2]);

                float r0 = fmaf(tanh_hw(gR.x + hR.x + cR0), 0.5f, 0.5f);
                float r1 = fmaf(tanh_hw(gR.y + hR.y + cR1), 0.5f, 0.5f);
                float z0 = fmaf(tanh_hw(gZ.x + hZ.x + cZ0), 0.5f, 0.5f);
                float z1 = fmaf(tanh_hw(gZ.y + hZ.y + cZ1), 0.5f, 0.5f);
                float n0 = tanh_hw(gN.x + biN0 + r0 * (hN.x + bhN0));
                float n1 = tanh_hw(gN.y + biN1 + r1 * (hN.y + bhN1));

                float ho0 = shf[bl * 68 + c2];
                float ho1 = shf[bl * 68 + c2 + 1];
                float hn0 = fmaf(z0, ho0 - n0, n0);
                float hn1 = fmaf(z1, ho1 - n1, n1);
                shf[bl * 68 + c2]     = hn0;
                shf[bl * 68 + c2 + 1] = hn1;
                reinterpret_cast<__half2*>(sHh)[bl * 36 + lane] =
                    __floats2half2_rn(hn0, hn1);
            }
        }
        __syncthreads();   // h (f32+fp16) visible before next step's mma
    }

    // ---- final output row: ys[pred_len-1] = h @ Wo + bo (exact butterfly) --
    #pragma unroll 1
    for (int i = 0; i < 4; i++) {
        const int bl = 4 * wrp + i;
        const int bg = b0 + bl;
        float h0 = shf[bl * 68 + lane];
        float h1 = shf[bl * 68 + 32 + lane];
        float s0 = h0 * wo0 + h1 * wo2;
        float s1 = h0 * wo1 + h1 * wo3;
        float x  = hi16 ? s1 : s0;
        float ys = hi16 ? s0 : s1;
        float v  = x + __shfl_xor_sync(FULLM, ys, 16);
        v += __shfl_xor_sync(FULLM, v, 8);
        v += __shfl_xor_sync(FULLM, v, 4);
        v += __shfl_xor_sync(FULLM, v, 2);
        v += __shfl_xor_sync(FULLM, v, 1);
        float w = __shfl_xor_sync(FULLM, v, 16);
        if (lane == 0) {
            *reinterpret_cast<float2*>(
                &out[((size_t)(pred_len - 1) * B + bg) * 2]) =
                make_float2(v + bo0, w + bo1);
        }
    }
}

// ---------------------------------------------------------------------------
// Host launcher: 2 kernels total.
// ---------------------------------------------------------------------------
extern "C" void kernel_launch(void* const* d_in, const int* in_sizes, int n_in,
                              void* d_out, int out_size)
{
    const int o = (in_sizes[0] == 1) ? 1 : 0;

    const float* lastx = (const float*)d_in[o + 0];
    const float* zo    = (const float*)d_in[o + 1];
    const float* inter = (const float*)d_in[o + 3];
    const float* We    = (const float*)d_in[o + 4];
    const float* be    = (const float*)d_in[o + 5];
    const float* Wih   = (const float*)d_in[o + 6];
    const float* Whh   = (const float*)d_in[o + 7];
    const float* bih   = (const float*)d_in[o + 8];
    const float* bhh   = (const float*)d_in[o + 9];
    const float* Wc1   = (const float*)d_in[o + 10];
    const float* bc1   = (const float*)d_in[o + 11];
    const float* Wc2   = (const float*)d_in[o + 12];
    const float* Wo    = (const float*)d_in[o + 14];
    const float* bo    = (const float*)d_in[o + 15];
    float* out = (float*)d_out;

    const int B = in_sizes[o + 0] / 2;
    const int pred_len = out_size / (2 * B);
    (void)n_in;

    static bool attr_done = false;
    if (!attr_done) {
        cudaFuncSetAttribute(step_kernel,
                             cudaFuncAttributeMaxDynamicSharedMemorySize,
                             SMEM_BYTES);
        attr_done = true;
    }

    precomp_kernel<<<(ND * B) / 64, 128>>>(inter, Wc1, bc1, We);

    step_kernel<<<B / BPB, 256, SMEM_BYTES>>>(lastx, zo, Wc1, Whh, bhh,
                                              Wih, bih, Wc2, We, be, Wo, bo,
                                              out, B, pred_len);
}

// round 14
// speedup vs baseline: 1.7771x; 1.0894x over previous
#include <cuda_runtime.h>
#include <cuda_fp16.h>
#include <cstdint>
#include <cstddef>

// Problem constants: B=16384, ND=20, D_G=D_H=64, D_EMB=16, pred_len=12.
#define MAXB 16384
#define ND 20
#define BPB 32          // batch elements per block (4 per warp, 8 warps)
#define FULLM 0xffffffffu

typedef unsigned long long ull;

// Time-invariant precompute scratch (fp16), batch-major layouts:
//   g_preh[b][n][k] : pre = inter@Wc1[:64]+bc1   (20*64 halfs = 2560 B per b)
//   g_igh [b][j][n] : ig  = inter@We[:64]        (16*20 halfs =  640 B per b)
__device__ __half g_preh[(size_t)MAXB * ND * 64];
__device__ __half g_igh [(size_t)MAXB * 16 * ND];

__device__ __forceinline__ float tanh_hw(float x) {
    float y; asm("tanh.approx.f32 %0, %1;" : "=f"(y) : "f"(x)); return y;
}
__device__ __forceinline__ float ex2_hw(float x) {
    float y; asm("ex2.approx.f32 %0, %1;" : "=f"(y) : "f"(x)); return y;
}
__device__ __forceinline__ ull pack2(float v) {
    ull r; asm("mov.b64 %0, {%1, %1};" : "=l"(r) : "f"(v)); return r;
}
__device__ __forceinline__ float2 unpack2(ull u) {
    float2 v; asm("mov.b64 {%0, %1}, %2;" : "=f"(v.x), "=f"(v.y) : "l"(u)); return v;
}

// ---------------------------------------------------------------------------
// Precompute (one pass over intermediate), writing batch-major fp16 layouts.
// Block handles 64 consecutive rows m of intermediate (m = n*B + b); since
// B % 64 == 0 the whole block shares one dest index n.
// ---------------------------------------------------------------------------
__global__ void precomp_kernel(const float* __restrict__ A,
                               const float* __restrict__ Wc1,
                               const float* __restrict__ bc1,
                               const float* __restrict__ We,
                               int B)
{
    __shared__ float As[64][68];
    __shared__ float Ws[64][80];

    const int tid = threadIdx.x;
    const int m0  = blockIdx.x * 64;
    const int nD  = m0 / B;            // dest index (constant per block)
    const int bb0 = m0 - nD * B;       // first batch index

    const float4* Ag = reinterpret_cast<const float4*>(A + (size_t)m0 * 64);
    #pragma unroll
    for (int i = 0; i < 8; i++) {
        int idx = tid + i * 128;
        int r = idx >> 4, k4 = (idx & 15) << 2;
        float4 v = Ag[idx];
        As[k4 + 0][r] = v.x; As[k4 + 1][r] = v.y;
        As[k4 + 2][r] = v.z; As[k4 + 3][r] = v.w;
    }
    for (int i = tid; i < 64 * 80; i += 128) {
        int k = i / 80, c = i - k * 80;
        Ws[k][c] = (c < 64) ? Wc1[k * 64 + c] : We[k * 16 + (c - 64)];
    }
    __syncthreads();

    const int tx = tid & 15;
    const int ty = tid >> 4;

    float acc[8][5];
    #pragma unroll
    for (int i = 0; i < 8; i++)
        #pragma unroll
        for (int j = 0; j < 5; j++) acc[i][j] = 0.f;

    #pragma unroll 4
    for (int k = 0; k < 64; k++) {
        float wv[5];
        #pragma unroll
        for (int j = 0; j < 5; j++) wv[j] = Ws[k][tx + 16 * j];
        float4 a0 = *reinterpret_cast<const float4*>(&As[k][ty << 3]);
        float4 a1 = *reinterpret_cast<const float4*>(&As[k][(ty << 3) + 4]);
        float av[8] = {a0.x, a0.y, a0.z, a0.w, a1.x, a1.y, a1.z, a1.w};
        #pragma unroll
        for (int i = 0; i < 8; i++)
            #pragma unroll
            for (int j = 0; j < 5; j++)
                acc[i][j] = fmaf(av[i], wv[j], acc[i][j]);
    }

    #pragma unroll
    for (int j = 0; j < 5; j++) {
        int c = tx + 16 * j;
        float bv = (c < 64) ? bc1[c] : 0.f;
        #pragma unroll
        for (int i = 0; i < 8; i++) {
            int b = bb0 + (ty << 3) + i;
            float v = acc[i][j] + bv;
            if (c < 64)
                g_preh[((size_t)b * ND + nD) * 64 + c] = __float2half_rn(v);
            else
                g_igh[(size_t)b * (16 * ND) + (c - 64) * ND + nD] = __float2half_rn(v);
        }
    }
}

// ---------------------------------------------------------------------------
// smem byte offsets
// sW2 : fp16 [64][280]  combined W cols: 0-63 hp, 64-127 r*.5, 128-191 z*.5,
//                        192-255 n, 256-257 Wo, 258-279 zero  (35840 B)
// sHh : fp16 [32][72]   h copy for mma A                      ( 4608 B)
// sG  : f32  [32][280]  GEMM result (hp|r|z|n|y)              (35840 B)
// sWih: f32  [16][192]  Wih (r/z cols pre-scaled 0.5)         (12288 B)
// ---------------------------------------------------------------------------
#define OFF_W2    0
#define OFF_HH    35840
#define OFF_G     40448
#define OFF_WIH   76288
#define OFF_HF    88576      // f32 [32][68] h                   8704 B
#define OFF_BIH   97280
#define OFF_BHH   98048
#define OFF_WO    98816
#define OFF_WC2   99328
#define OFF_WEY   99584
#define OFF_BE    99712
#define OFF_BO    99776
#define SMEM_BYTES 99784

#define W2_STRIDE_B 560      // 280 halfs
#define HH_STRIDE_B 144      // 72 halfs
#define G_STRIDE    280      // f32

__device__ __forceinline__ uint32_t smem_u32(const void* p) {
    return (uint32_t)__cvta_generic_to_shared(p);
}

#define LDMX4(r0,r1,r2,r3,addr) \
    asm volatile("ldmatrix.sync.aligned.m8n8.x4.shared.b16 {%0,%1,%2,%3}, [%4];" \
        : "=r"(r0),"=r"(r1),"=r"(r2),"=r"(r3) : "r"(addr))
#define LDMX4T(r0,r1,r2,r3,addr) \
    asm volatile("ldmatrix.sync.aligned.m8n8.x4.trans.shared.b16 {%0,%1,%2,%3}, [%4];" \
        : "=r"(r0),"=r"(r1),"=r"(r2),"=r"(r3) : "r"(addr))
#define LDMX2T(r0,r1,addr) \
    asm volatile("ldmatrix.sync.aligned.m8n8.x2.trans.shared.b16 {%0,%1}, [%2];" \
        : "=r"(r0),"=r"(r1) : "r"(addr))
#define MMA16816(d0,d1,d2,d3,a0,a1,a2,a3,b0,b1) \
    asm volatile("mma.sync.aligned.m16n8k16.row.col.f32.f16.f16.f32 " \
        "{%0,%1,%2,%3}, {%4,%5,%6,%7}, {%8,%9}, {%0,%1,%2,%3};" \
        : "+f"(d0),"+f"(d1),"+f"(d2),"+f"(d3) \
        : "r"(a0),"r"(a1),"r"(a2),"r"(a3),"r"(b0),"r"(b1))

__global__ void __launch_bounds__(256, 2)
step_kernel(const float* __restrict__ lastx,
            const float* __restrict__ zo,
            const float* __restrict__ Wc1,
            const float* __restrict__ Whh,
            const float* __restrict__ bhh,
            const float* __restrict__ Wih,
            const float* __restrict__ bih,
            const float* __restrict__ Wc2,
            const float* __restrict__ We,
            const float* __restrict__ be,
            const float* __restrict__ Wo,
            const float* __restrict__ bo,
            float* __restrict__ out,
            int B, int pred_len)
{
    extern __shared__ char smc[];
    __half* sW2h  = reinterpret_cast<__half*>(smc + OFF_W2);
    __half* sHh   = reinterpret_cast<__half*>(smc + OFF_HH);
    float*  sG    = reinterpret_cast<float*>(smc + OFF_G);
    float*  sWih  = reinterpret_cast<float*>(smc + OFF_WIH);
    float*  shf   = reinterpret_cast<float*>(smc + OFF_HF);
    float*  sbih  = reinterpret_cast<float*>(smc + OFF_BIH);
    float*  sbhh  = reinterpret_cast<float*>(smc + OFF_BHH);
    float*  sWo   = reinterpret_cast<float*>(smc + OFF_WO);
    float*  sWc2  = reinterpret_cast<float*>(smc + OFF_WC2);
    float*  sWeY  = reinterpret_cast<float*>(smc + OFF_WEY);
    float*  sbe   = reinterpret_cast<float*>(smc + OFF_BE);
    float*  sbo   = reinterpret_cast<float*>(smc + OFF_BO);

    const int tid  = threadIdx.x;
    const int lane = tid & 31;
    const int wrp  = tid >> 5;
    const int b0   = blockIdx.x * BPB;

    // ---- init weights ----
    for (int i = tid; i < 64 * 280; i += 256) {
        int k = i / 280, c = i - k * 280;
        float v;
        if      (c < 64)  v = Wc1[(64 + k) * 64 + c];
        else if (c < 128) v = 0.5f * Whh[k * 192 + (c - 64)];
        else if (c < 192) v = 0.5f * Whh[k * 192 + 64 + (c - 128)];
        else if (c < 256) v = Whh[k * 192 + 128 + (c - 192)];
        else if (c == 256) v = Wo[k * 2];
        else if (c == 257) v = Wo[k * 2 + 1];
        else v = 0.f;
        sW2h[k * 280 + c] = __float2half(v);
    }
    for (int i = tid; i < 16 * 192; i += 256) {
        int c = i % 192;
        float v = Wih[i];
        if (c < 128) v *= 0.5f;
        sWih[i] = v;
    }
    if (tid < 192) { sbih[tid] = bih[tid]; sbhh[tid] = bhh[tid]; }
    if (tid < 128) sWo[tid]  = Wo[tid];
    if (tid < 64)  sWc2[tid] = Wc2[tid];
    if (tid < 32)  sWeY[tid] = We[64 * 16 + tid];
    if (tid < 16)  sbe[tid]  = be[tid];
    if (tid < 2)   sbo[tid]  = bo[tid];
    for (int i = tid; i < BPB * 64; i += 256) {
        int r = i >> 6, k = i & 63;
        float v = zo[(size_t)(b0 + r) * 64 + k];
        shf[r * 68 + k] = v;
        sHh[r * 72 + k] = __float2half(v);
    }
    for (int i = tid; i < BPB * 8; i += 256) {
        int r = i >> 3, k = 64 + (i & 7);
        sHh[r * 72 + k] = __float2half(0.f);
    }
    __syncthreads();

    // ---- hoisted per-lane constants ----
    const int   c2  = 2 * lane;
    const int   lane16 = lane & 15;
    const bool  hi16 = (lane & 16) != 0;
    const float LOG2E = 1.4426950408889634f;
    // Wc2 for k = 4*lane16 .. +3, log2e folded
    const float w40 = sWc2[4 * lane16 + 0] * LOG2E;
    const float w41 = sWc2[4 * lane16 + 1] * LOG2E;
    const float w42 = sWc2[4 * lane16 + 2] * LOG2E;
    const float w43 = sWc2[4 * lane16 + 3] * LOG2E;
    const float wo0 = sWo[lane * 2],        wo1 = sWo[lane * 2 + 1];
    const float wo2 = sWo[(lane + 32) * 2], wo3 = sWo[(lane + 32) * 2 + 1];
    const float bo0 = sbo[0], bo1 = sbo[1];
    const float cR0 = 0.5f * (sbih[c2]          + sbhh[c2]);
    const float cR1 = 0.5f * (sbih[c2 + 1]      + sbhh[c2 + 1]);
    const float cZ0 = 0.5f * (sbih[64 + c2]     + sbhh[64 + c2]);
    const float cZ1 = 0.5f * (sbih[64 + c2 + 1] + sbhh[64 + c2 + 1]);
    const float biN0 = sbih[128 + c2],  biN1 = sbih[128 + c2 + 1];
    const float bhN0 = sbhh[128 + c2],  bhN1 = sbhh[128 + c2 + 1];
    const float weY0 = sWeY[lane16];
    const float weY1 = sWeY[16 + lane16];
    const float bev  = sbe[lane16];

    // ---- mma addressing (per-lane, hoisted) ----
    const int mb = 16 * (wrp & 1);
    const int nb = 64 * (wrp >> 1);
    const int sub = lane >> 3, srw = lane & 7;
    const uint32_t hhBase = smem_u32(sHh);
    const uint32_t w2Base = smem_u32(sW2h);
    const uint32_t aAddr0 = hhBase + (uint32_t)((mb + srw + 8 * (sub & 1)) * HH_STRIDE_B
                                                + (8 * (sub >> 1)) * 2);
    const uint32_t bAddr0 = w2Base + (uint32_t)((srw + 8 * (sub & 1)) * W2_STRIDE_B
                                                + (nb + 8 * (sub >> 1)) * 2);
    const uint32_t yAddr0 = w2Base + (uint32_t)(((lane & 7) + 8 * ((lane >> 3) & 1)) * W2_STRIDE_B
                                                + 256 * 2);

    // Per-lane bases into the batch-major pre/ig (row term added per row)
    const int preLaneOff = (hi16 ? 64 : 0) + 4 * lane16;   // halfs
    const int igLaneOff  = lane16 * ND;                    // halfs

    for (int t = 0; t < pred_len; t++) {
        // ============ Phase A: tensor-core GEMM  sG = h_fp16 @ W_fp16 =======
        {
            float d[8][4];
            #pragma unroll
            for (int j = 0; j < 8; j++)
                #pragma unroll
                for (int q = 0; q < 4; q++) d[j][q] = 0.f;
            float e[4] = {0.f, 0.f, 0.f, 0.f};

            #pragma unroll
            for (int kt = 0; kt < 4; kt++) {
                uint32_t a0, a1, a2, a3;
                LDMX4(a0, a1, a2, a3, aAddr0 + kt * 32);
                uint32_t bb = bAddr0 + kt * (16 * W2_STRIDE_B);
                #pragma unroll
                for (int ng = 0; ng < 4; ng++) {
                    uint32_t q0, q1, q2, q3;
                    LDMX4T(q0, q1, q2, q3, bb + ng * 32);
                    MMA16816(d[2*ng][0], d[2*ng][1], d[2*ng][2], d[2*ng][3],
                             a0, a1, a2, a3, q0, q1);
                    MMA16816(d[2*ng+1][0], d[2*ng+1][1], d[2*ng+1][2], d[2*ng+1][3],
                             a0, a1, a2, a3, q2, q3);
                }
                if (wrp < 2) {
                    uint32_t y0r, y1r;
                    LDMX2T(y0r, y1r, yAddr0 + kt * (16 * W2_STRIDE_B));
                    MMA16816(e[0], e[1], e[2], e[3], a0, a1, a2, a3, y0r, y1r);
                }
            }
            const int gr = mb + (lane >> 2);
            const int gc = nb + 2 * (lane & 3);
            #pragma unroll
            for (int j = 0; j < 8; j++) {
                int col = gc + 8 * j;
                *reinterpret_cast<float2*>(&sG[gr * G_STRIDE + col]) =
                    make_float2(d[j][0], d[j][1]);
                *reinterpret_cast<float2*>(&sG[(gr + 8) * G_STRIDE + col]) =
                    make_float2(d[j][2], d[j][3]);
            }
            if (wrp < 2) {
                int col = 256 + 2 * (lane & 3);
                *reinterpret_cast<float2*>(&sG[gr * G_STRIDE + col]) =
                    make_float2(e[0], e[1]);
                *reinterpret_cast<float2*>(&sG[(gr + 8) * G_STRIDE + col]) =
                    make_float2(e[2], e[3]);
            }
        }
        __syncthreads();

        // ============ Phase B: y + online attention per row -> embv[i] ======
        float embv[4];
        #pragma unroll 1
        for (int i = 0; i < 4; i++) {
            const int bl = 4 * wrp + i;
            const int bg = b0 + bl;

            float y0, y1;
            if (t == 0) {
                y0 = lastx[2 * bg];
                y1 = lastx[2 * bg + 1];
            } else {
                float2 yv = *reinterpret_cast<const float2*>(&sG[bl * G_STRIDE + 256]);
                y0 = yv.x + bo0;
                y1 = yv.y + bo1;
                if (lane == 0) {
                    *reinterpret_cast<float2*>(
                        &out[((size_t)(t - 1) * B + bg) * 2]) = make_float2(y0, y1);
                }
            }

            // hp at k = 4*lane16 .. +3 (one LDS.128)
            const float4 hp4 = *reinterpret_cast<const float4*>(
                &sG[bl * G_STRIDE + 4 * lane16]);
            const __half* pb_ = g_preh + (size_t)bg * (ND * 64) + preLaneOff;
            const __half* ib_ = g_igh  + (size_t)bg * (16 * ND) + igLaneOff;

            float ssum = 0.f, wa = 0.f;
            #pragma unroll
            for (int n = 0; n < ND; n += 2) {
                // lanes 0-15: dest n, lanes 16-31: dest n+1 (one LDG.64 each)
                uint2 pr = *reinterpret_cast<const uint2*>(pb_ + n * 64);
                float2 pA = __half22float2(*reinterpret_cast<__half2*>(&pr.x));
                float2 pB = __half22float2(*reinterpret_cast<__half2*>(&pr.y));
                float c = tanh_hw(pA.x + hp4.x) * w40;
                c = fmaf(tanh_hw(pA.y + hp4.y), w41, c);
                c = fmaf(tanh_hw(pB.x + hp4.z), w42, c);
                c = fmaf(tanh_hw(pB.y + hp4.w), w43, c);
                c += __shfl_xor_sync(FULLM, c, 8);
                c += __shfl_xor_sync(FULLM, c, 4);
                c += __shfl_xor_sync(FULLM, c, 2);
                c += __shfl_xor_sync(FULLM, c, 1);
                float w = __shfl_xor_sync(FULLM, c, 16);
                float e0 = ex2_hw(hi16 ? w : c);     // exp(compab[n])
                float e1 = ex2_hw(hi16 ? c : w);     // exp(compab[n+1])
                ssum += e0 + e1;
                float2 ig2 = __half22float2(
                    *reinterpret_cast<const __half2*>(ib_ + n));
                wa = fmaf(e0, ig2.x, fmaf(e1, ig2.y, wa));
            }
            const float inv = 1.f / ssum;
            embv[i] = fmaf(wa, inv, fmaf(y0, weY0, fmaf(y1, weY1, bev)));
        }

        // ============ Phase C: GRU (f32 Wih, shared across row pairs) =======
        #pragma unroll
        for (int p = 0; p < 2; p++) {
            ull aR0 = 0ull, aZ0 = 0ull, aN0 = 0ull;
            ull aR1 = 0ull, aZ1 = 0ull, aN1 = 0ull;
            #pragma unroll
            for (int k = 0; k < 16; k++) {
                ull wr = *reinterpret_cast<const ull*>(&sWih[k * 192 + c2]);
                ull wz = *reinterpret_cast<const ull*>(&sWih[k * 192 + 64 + c2]);
                ull wn = *reinterpret_cast<const ull*>(&sWih[k * 192 + 128 + c2]);
                ull e20 = pack2(__shfl_sync(FULLM, embv[2 * p],     k));
                ull e21 = pack2(__shfl_sync(FULLM, embv[2 * p + 1], k));
                asm("fma.rn.f32x2 %0, %1, %2, %0;" : "+l"(aR0) : "l"(e20), "l"(wr));
                asm("fma.rn.f32x2 %0, %1, %2, %0;" : "+l"(aZ0) : "l"(e20), "l"(wz));
                asm("fma.rn.f32x2 %0, %1, %2, %0;" : "+l"(aN0) : "l"(e20), "l"(wn));
                asm("fma.rn.f32x2 %0, %1, %2, %0;" : "+l"(aR1) : "l"(e21), "l"(wr));
                asm("fma.rn.f32x2 %0, %1, %2, %0;" : "+l"(aZ1) : "l"(e21), "l"(wz));
                asm("fma.rn.f32x2 %0, %1, %2, %0;" : "+l"(aN1) : "l"(e21), "l"(wn));
            }
            #pragma unroll
            for (int q = 0; q < 2; q++) {
                const int i  = 2 * p + q;
                const int bl = 4 * wrp + i;
                float2 gR = unpack2(q == 0 ? aR0 : aR1);
                float2 gZ = unpack2(q == 0 ? aZ0 : aZ1);
                float2 gN = unpack2(q == 0 ? aN0 : aN1);
                float2 hR = *reinterpret_cast<const float2*>(&sG[bl * G_STRIDE + 64 + c2]);
                float2 hZ = *reinterpret_cast<const float2*>(&sG[bl * G_STRIDE + 128 + c2]);
                float2 hN = *reinterpret_cast<const float2*>(&sG[bl * G_STRIDE + 192 + c2]);

                float r0 = fmaf(tanh_hw(gR.x + hR.x + cR0), 0.5f, 0.5f);
                float r1 = fmaf(tanh_hw(gR.y + hR.y + cR1), 0.5f, 0.5f);
                float z0 = fmaf(tanh_hw(gZ.x + hZ.x + cZ0), 0.5f, 0.5f);
                float z1 = fmaf(tanh_hw(gZ.y + hZ.y + cZ1), 0.5f, 0.5f);
                float n0 = tanh_hw(gN.x + biN0 + r0 * (hN.x + bhN0));
                float n1 = tanh_hw(gN.y + biN1 + r1 * (hN.y + bhN1));

                float ho0 = shf[bl * 68 + c2];
                float ho1 = shf[bl * 68 + c2 + 1];
                float hn0 = fmaf(z0, ho0 - n0, n0);
                float hn1 = fmaf(z1, ho1 - n1, n1);
                shf[bl * 68 + c2]     = hn0;
                shf[bl * 68 + c2 + 1] = hn1;
                reinterpret_cast<__half2*>(sHh)[bl * 36 + lane] =
                    __floats2half2_rn(hn0, hn1);
            }
        }
        __syncthreads();   // h (f32+fp16) visible before next step's mma
    }

    // ---- final output row: ys[pred_len-1] = h @ Wo + bo ----
    #pragma unroll 1
    for (int i = 0; i < 4; i++) {
        const int bl = 4 * wrp + i;
        const int bg = b0 + bl;
        float h0 = shf[bl * 68 + lane];
        float h1 = shf[bl * 68 + 32 + lane];
        float s0 = h0 * wo0 + h1 * wo2;
        float s1 = h0 * wo1 + h1 * wo3;
        float x  = hi16 ? s1 : s0;
        float ys = hi16 ? s0 : s1;
        float v  = x + __shfl_xor_sync(FULLM, ys, 16);
        v += __shfl_xor_sync(FULLM, v, 8);
        v += __shfl_xor_sync(FULLM, v, 4);
        v += __shfl_xor_sync(FULLM, v, 2);
        v += __shfl_xor_sync(FULLM, v, 1);
        float w = __shfl_xor_sync(FULLM, v, 16);
        if (lane == 0) {
            *reinterpret_cast<float2*>(
                &out[((size_t)(pred_len - 1) * B + bg) * 2]) =
                make_float2(v + bo0, w + bo1);
        }
    }
}

// ---------------------------------------------------------------------------
// Host launcher: 2 kernels total.
// ---------------------------------------------------------------------------
extern "C" void kernel_launch(void* const* d_in, const int* in_sizes, int n_in,
                              void* d_out, int out_size)
{
    const int o = (in_sizes[0] == 1) ? 1 : 0;

    const float* lastx = (const float*)d_in[o + 0];
    const float* zo    = (const float*)d_in[o + 1];
    const float* inter = (const float*)d_in[o + 3];
    const float* We    = (const float*)d_in[o + 4];
    const float* be    = (const float*)d_in[o + 5];
    const float* Wih   = (const float*)d_in[o + 6];
    const float* Whh   = (const float*)d_in[o + 7];
    const float* bih   = (const float*)d_in[o + 8];
    const float* bhh   = (const float*)d_in[o + 9];
    const float* Wc1   = (const float*)d_in[o + 10];
    const float* bc1   = (const float*)d_in[o + 11];
    const float* Wc2   = (const float*)d_in[o + 12];
    const float* Wo    = (const float*)d_in[o + 14];
    const float* bo    = (const float*)d_in[o + 15];
    float* out = (float*)d_out;

    const int B = in_sizes[o + 0] / 2;
    const int pred_len = out_size / (2 * B);
    (void)n_in;

    static bool attr_done = false;
    if (!attr_done) {
        cudaFuncSetAttribute(step_kernel,
                             cudaFuncAttributeMaxDynamicSharedMemorySize,
                             SMEM_BYTES);
        attr_done = true;
    }

    precomp_kernel<<<(ND * B) / 64, 128>>>(inter, Wc1, bc1, We, B);

    step_kernel<<<B / BPB, 256, SMEM_BYTES>>>(lastx, zo, Wc1, Whh, bhh,
                                              Wih, bih, Wc2, We, be, Wo, bo,
                                              out, B, pred_len);
}

// round 17
// speedup vs baseline: 1.8104x; 1.0187x over previous
#include <cuda_runtime.h>
#include <cuda_fp16.h>
#include <cstdint>
#include <cstddef>

// Problem constants: B=16384, ND=20, D_G=D_H=64, D_EMB=16, pred_len=12.
#define MAXB 16384
#define ND 20
#define BPB 32          // batch elements per block (4 per warp, 8 warps)
#define FULLM 0xffffffffu

typedef unsigned long long ull;

// Time-invariant precompute scratch (fp16), batch-major layouts:
//   g_preh[b][n][k] : pre = inter@Wc1[:64]+bc1   (20*64 halfs = 2560 B per b)
//   g_igh [b][j][n] : ig  = inter@We[:64]        (16*20 halfs =  640 B per b)
__device__ __half g_preh[(size_t)MAXB * ND * 64];
__device__ __half g_igh [(size_t)MAXB * 16 * ND];

__device__ __forceinline__ float tanh_hw(float x) {
    float y; asm("tanh.approx.f32 %0, %1;" : "=f"(y) : "f"(x)); return y;
}
__device__ __forceinline__ float ex2_hw(float x) {
    float y; asm("ex2.approx.f32 %0, %1;" : "=f"(y) : "f"(x)); return y;
}
__device__ __forceinline__ ull pack2(float v) {
    ull r; asm("mov.b64 %0, {%1, %1};" : "=l"(r) : "f"(v)); return r;
}
__device__ __forceinline__ float2 unpack2(ull u) {
    float2 v; asm("mov.b64 {%0, %1}, %2;" : "=f"(v.x), "=f"(v.y) : "l"(u)); return v;
}

// ---------------------------------------------------------------------------
// Precompute (one pass over intermediate), writing batch-major fp16 layouts.
// ---------------------------------------------------------------------------
__global__ void precomp_kernel(const float* __restrict__ A,
                               const float* __restrict__ Wc1,
                               const float* __restrict__ bc1,
                               const float* __restrict__ We,
                               int B)
{
    __shared__ float As[64][68];
    __shared__ float Ws[64][80];

    const int tid = threadIdx.x;
    const int m0  = blockIdx.x * 64;
    const int nD  = m0 / B;            // dest index (constant per block)
    const int bb0 = m0 - nD * B;       // first batch index

    const float4* Ag = reinterpret_cast<const float4*>(A + (size_t)m0 * 64);
    #pragma unroll
    for (int i = 0; i < 8; i++) {
        int idx = tid + i * 128;
        int r = idx >> 4, k4 = (idx & 15) << 2;
        float4 v = Ag[idx];
        As[k4 + 0][r] = v.x; As[k4 + 1][r] = v.y;
        As[k4 + 2][r] = v.z; As[k4 + 3][r] = v.w;
    }
    for (int i = tid; i < 64 * 80; i += 128) {
        int k = i / 80, c = i - k * 80;
        Ws[k][c] = (c < 64) ? Wc1[k * 64 + c] : We[k * 16 + (c - 64)];
    }
    __syncthreads();

    const int tx = tid & 15;
    const int ty = tid >> 4;

    float acc[8][5];
    #pragma unroll
    for (int i = 0; i < 8; i++)
        #pragma unroll
        for (int j = 0; j < 5; j++) acc[i][j] = 0.f;

    #pragma unroll 4
    for (int k = 0; k < 64; k++) {
        float wv[5];
        #pragma unroll
        for (int j = 0; j < 5; j++) wv[j] = Ws[k][tx + 16 * j];
        float4 a0 = *reinterpret_cast<const float4*>(&As[k][ty << 3]);
        float4 a1 = *reinterpret_cast<const float4*>(&As[k][(ty << 3) + 4]);
        float av[8] = {a0.x, a0.y, a0.z, a0.w, a1.x, a1.y, a1.z, a1.w};
        #pragma unroll
        for (int i = 0; i < 8; i++)
            #pragma unroll
            for (int j = 0; j < 5; j++)
                acc[i][j] = fmaf(av[i], wv[j], acc[i][j]);
    }

    #pragma unroll
    for (int j = 0; j < 5; j++) {
        int c = tx + 16 * j;
        float bv = (c < 64) ? bc1[c] : 0.f;
        #pragma unroll
        for (int i = 0; i < 8; i++) {
            int b = bb0 + (ty << 3) + i;
            float v = acc[i][j] + bv;
            if (c < 64)
                g_preh[((size_t)b * ND + nD) * 64 + c] = __float2half_rn(v);
            else
                g_igh[(size_t)b * (16 * ND) + (c - 64) * ND + nD] = __float2half_rn(v);
        }
    }
}

// ---------------------------------------------------------------------------
// smem byte offsets
// ---------------------------------------------------------------------------
#define OFF_W2    0          // fp16 [64][280]
#define OFF_HH    35840      // fp16 [32][72]
#define OFF_G     40448      // f32  [32][280]
#define OFF_WIH   76288      // f32  [16][192]
#define OFF_HF    88576      // f32  [32][68]
#define OFF_BIH   97280
#define OFF_BHH   98048
#define OFF_WO    98816
#define OFF_WC2   99328
#define OFF_WEY   99584
#define OFF_BE    99712
#define OFF_BO    99776
#define SMEM_BYTES 99784

#define W2_STRIDE_B 560      // 280 halfs
#define HH_STRIDE_B 144      // 72 halfs
#define G_STRIDE    280      // f32

__device__ __forceinline__ uint32_t smem_u32(const void* p) {
    return (uint32_t)__cvta_generic_to_shared(p);
}

#define LDMX4(r0,r1,r2,r3,addr) \
    asm volatile("ldmatrix.sync.aligned.m8n8.x4.shared.b16 {%0,%1,%2,%3}, [%4];" \
        : "=r"(r0),"=r"(r1),"=r"(r2),"=r"(r3) : "r"(addr))
#define LDMX4T(r0,r1,r2,r3,addr) \
    asm volatile("ldmatrix.sync.aligned.m8n8.x4.trans.shared.b16 {%0,%1,%2,%3}, [%4];" \
        : "=r"(r0),"=r"(r1),"=r"(r2),"=r"(r3) : "r"(addr))
#define LDMX2T(r0,r1,addr) \
    asm volatile("ldmatrix.sync.aligned.m8n8.x2.trans.shared.b16 {%0,%1}, [%2];" \
        : "=r"(r0),"=r"(r1) : "r"(addr))
#define MMA16816(d0,d1,d2,d3,a0,a1,a2,a3,b0,b1) \
    asm volatile("mma.sync.aligned.m16n8k16.row.col.f32.f16.f16.f32 " \
        "{%0,%1,%2,%3}, {%4,%5,%6,%7}, {%8,%9}, {%0,%1,%2,%3};" \
        : "+f"(d0),"+f"(d1),"+f"(d2),"+f"(d3) \
        : "r"(a0),"r"(a1),"r"(a2),"r"(a3),"r"(b0),"r"(b1))

// Named barrier over 128 threads (two independent block halves)
#define HALF_BAR(id) asm volatile("bar.sync %0, 128;" :: "r"(id) : "memory")

__global__ void __launch_bounds__(256, 2)
step_kernel(const float* __restrict__ lastx,
            const float* __restrict__ zo,
            const float* __restrict__ Wc1,
            const float* __restrict__ Whh,
            const float* __restrict__ bhh,
            const float* __restrict__ Wih,
            const float* __restrict__ bih,
            const float* __restrict__ Wc2,
            const float* __restrict__ We,
            const float* __restrict__ be,
            const float* __restrict__ Wo,
            const float* __restrict__ bo,
            float* __restrict__ out,
            int B, int pred_len)
{
    extern __shared__ char smc[];
    __half* sW2h  = reinterpret_cast<__half*>(smc + OFF_W2);
    __half* sHh   = reinterpret_cast<__half*>(smc + OFF_HH);
    float*  sG    = reinterpret_cast<float*>(smc + OFF_G);
    float*  sWih  = reinterpret_cast<float*>(smc + OFF_WIH);
    float*  shf   = reinterpret_cast<float*>(smc + OFF_HF);
    float*  sbih  = reinterpret_cast<float*>(smc + OFF_BIH);
    float*  sbhh  = reinterpret_cast<float*>(smc + OFF_BHH);
    float*  sWo   = reinterpret_cast<float*>(smc + OFF_WO);
    float*  sWc2  = reinterpret_cast<float*>(smc + OFF_WC2);
    float*  sWeY  = reinterpret_cast<float*>(smc + OFF_WEY);
    float*  sbe   = reinterpret_cast<float*>(smc + OFF_BE);
    float*  sbo   = reinterpret_cast<float*>(smc + OFF_BO);

    const int tid  = threadIdx.x;
    const int lane = tid & 31;
    const int wrp  = tid >> 5;
    const int grp  = wrp >> 2;          // block half: 0 (rows 0-15) / 1 (16-31)
    const int b0   = blockIdx.x * BPB;

    // ---- init weights ----
    for (int i = tid; i < 64 * 280; i += 256) {
        int k = i / 280, c = i - k * 280;
        float v;
        if      (c < 64)  v = Wc1[(64 + k) * 64 + c];
        else if (c < 128) v = 0.5f * Whh[k * 192 + (c - 64)];
        else if (c < 192) v = 0.5f * Whh[k * 192 + 64 + (c - 128)];
        else if (c < 256) v = Whh[k * 192 + 128 + (c - 192)];
        else if (c == 256) v = Wo[k * 2];
        else if (c == 257) v = Wo[k * 2 + 1];
        else v = 0.f;
        sW2h[k * 280 + c] = __float2half(v);
    }
    for (int i = tid; i < 16 * 192; i += 256) {
        int c = i % 192;
        float v = Wih[i];
        if (c < 128) v *= 0.5f;
        sWih[i] = v;
    }
    if (tid < 192) { sbih[tid] = bih[tid]; sbhh[tid] = bhh[tid]; }
    if (tid < 128) sWo[tid]  = Wo[tid];
    if (tid < 64)  sWc2[tid] = Wc2[tid];
    if (tid < 32)  sWeY[tid] = We[64 * 16 + tid];
    if (tid < 16)  sbe[tid]  = be[tid];
    if (tid < 2)   sbo[tid]  = bo[tid];
    for (int i = tid; i < BPB * 64; i += 256) {
        int r = i >> 6, k = i & 63;
        float v = zo[(size_t)(b0 + r) * 64 + k];
        shf[r * 68 + k] = v;
        sHh[r * 72 + k] = __float2half(v);
    }
    for (int i = tid; i < BPB * 8; i += 256) {
        int r = i >> 3, k = 64 + (i & 7);
        sHh[r * 72 + k] = __float2half(0.f);
    }
    __syncthreads();

    // ---- hoisted per-lane constants ----
    const int   c2  = 2 * lane;
    const int   lane16 = lane & 15;
    const bool  hi16 = (lane & 16) != 0;
    const float LOG2E = 1.4426950408889634f;
    const float w40 = sWc2[4 * lane16 + 0] * LOG2E;
    const float w41 = sWc2[4 * lane16 + 1] * LOG2E;
    const float w42 = sWc2[4 * lane16 + 2] * LOG2E;
    const float w43 = sWc2[4 * lane16 + 3] * LOG2E;
    const float wo0 = sWo[lane * 2],        wo1 = sWo[lane * 2 + 1];
    const float wo2 = sWo[(lane + 32) * 2], wo3 = sWo[(lane + 32) * 2 + 1];
    const float bo0 = sbo[0], bo1 = sbo[1];
    const float cR0 = 0.5f * (sbih[c2]          + sbhh[c2]);
    const float cR1 = 0.5f * (sbih[c2 + 1]      + sbhh[c2 + 1]);
    const float cZ0 = 0.5f * (sbih[64 + c2]     + sbhh[64 + c2]);
    const float cZ1 = 0.5f * (sbih[64 + c2 + 1] + sbhh[64 + c2 + 1]);
    const float biN0 = sbih[128 + c2],  biN1 = sbih[128 + c2 + 1];
    const float bhN0 = sbhh[128 + c2],  bhN1 = sbhh[128 + c2 + 1];
    const float weY0 = sWeY[lane16];
    const float weY1 = sWeY[16 + lane16];
    const float bev  = sbe[lane16];

    // ---- mma addressing: half-block decoupling ----
    // Group g (warps 4g..4g+3) produces AND consumes sG rows 16g..16g+15.
    const int mb = 16 * grp;
    const int nb = 64 * (wrp & 3);
    const bool yWarp = (wrp & 3) == 0;
    const int sub = lane >> 3, srw = lane & 7;
    const uint32_t hhBase = smem_u32(sHh);
    const uint32_t w2Base = smem_u32(sW2h);
    const uint32_t aAddr0 = hhBase + (uint32_t)((mb + srw + 8 * (sub & 1)) * HH_STRIDE_B
                                                + (8 * (sub >> 1)) * 2);
    const uint32_t bAddr0 = w2Base + (uint32_t)((srw + 8 * (sub & 1)) * W2_STRIDE_B
                                                + (nb + 8 * (sub >> 1)) * 2);
    const uint32_t yAddr0 = w2Base + (uint32_t)(((lane & 7) + 8 * ((lane >> 3) & 1)) * W2_STRIDE_B
                                                + 256 * 2);

    const int preLaneOff = (hi16 ? 64 : 0) + 4 * lane16;   // halfs
    const int igLaneOff  = lane16 * ND;                    // halfs

    for (int t = 0; t < pred_len; t++) {
        // ============ Phase A: tensor-core GEMM  sG = h_fp16 @ W_fp16 =======
        {
            float d[8][4];
            #pragma unroll
            for (int j = 0; j < 8; j++)
                #pragma unroll
                for (int q = 0; q < 4; q++) d[j][q] = 0.f;
            float e[4] = {0.f, 0.f, 0.f, 0.f};

            #pragma unroll
            for (int kt = 0; kt < 4; kt++) {
                uint32_t a0, a1, a2, a3;
                LDMX4(a0, a1, a2, a3, aAddr0 + kt * 32);
                uint32_t bb = bAddr0 + kt * (16 * W2_STRIDE_B);
                #pragma unroll
                for (int ng = 0; ng < 4; ng++) {
                    uint32_t q0, q1, q2, q3;
                    LDMX4T(q0, q1, q2, q3, bb + ng * 32);
                    MMA16816(d[2*ng][0], d[2*ng][1], d[2*ng][2], d[2*ng][3],
                             a0, a1, a2, a3, q0, q1);
                    MMA16816(d[2*ng+1][0], d[2*ng+1][1], d[2*ng+1][2], d[2*ng+1][3],
                             a0, a1, a2, a3, q2, q3);
                }
                if (yWarp) {
                    uint32_t y0r, y1r;
                    LDMX2T(y0r, y1r, yAddr0 + kt * (16 * W2_STRIDE_B));
                    MMA16816(e[0], e[1], e[2], e[3], a0, a1, a2, a3, y0r, y1r);
                }
            }
            const int gr = mb + (lane >> 2);
            const int gc = nb + 2 * (lane & 3);
            #pragma unroll
            for (int j = 0; j < 8; j++) {
                int col = gc + 8 * j;
                *reinterpret_cast<float2*>(&sG[gr * G_STRIDE + col]) =
                    make_float2(d[j][0], d[j][1]);
                *reinterpret_cast<float2*>(&sG[(gr + 8) * G_STRIDE + col]) =
                    make_float2(d[j][2], d[j][3]);
            }
            if (yWarp) {
                int col = 256 + 2 * (lane & 3);
                *reinterpret_cast<float2*>(&sG[gr * G_STRIDE + col]) =
                    make_float2(e[0], e[1]);
                *reinterpret_cast<float2*>(&sG[(gr + 8) * G_STRIDE + col]) =
                    make_float2(e[2], e[3]);
            }
        }
        HALF_BAR(1 + grp);

        // ============ Phase B: y + online attention per row -> embv[i] ======
        float embv[4];
        #pragma unroll 1
        for (int i = 0; i < 4; i++) {
            const int bl = 4 * wrp + i;
            const int bg = b0 + bl;

            float y0, y1;
            if (t == 0) {
                y0 = lastx[2 * bg];
                y1 = lastx[2 * bg + 1];
            } else {
                float2 yv = *reinterpret_cast<const float2*>(&sG[bl * G_STRIDE + 256]);
                y0 = yv.x + bo0;
                y1 = yv.y + bo1;
                if (lane == 0) {
                    *reinterpret_cast<float2*>(
                        &out[((size_t)(t - 1) * B + bg) * 2]) = make_float2(y0, y1);
                }
            }

            const float4 hp4 = *reinterpret_cast<const float4*>(
                &sG[bl * G_STRIDE + 4 * lane16]);
            const __half* pb_ = g_preh + (size_t)bg * (ND * 64) + preLaneOff;
            const __half* ib_ = g_igh  + (size_t)bg * (16 * ND) + igLaneOff;

            float ssum = 0.f, wa = 0.f;
            #pragma unroll
            for (int n = 0; n < ND; n += 2) {
                // lanes 0-15: dest n, lanes 16-31: dest n+1 (one LDG.64 each)
                uint2 pr = *reinterpret_cast<const uint2*>(pb_ + n * 64);
                float2 pA = __half22float2(*reinterpret_cast<__half2*>(&pr.x));
                float2 pB = __half22float2(*reinterpret_cast<__half2*>(&pr.y));
                float c = tanh_hw(pA.x + hp4.x) * w40;
                c = fmaf(tanh_hw(pA.y + hp4.y), w41, c);
                c = fmaf(tanh_hw(pB.x + hp4.z), w42, c);
                c = fmaf(tanh_hw(pB.y + hp4.w), w43, c);
                c += __shfl_xor_sync(FULLM, c, 8);
                c += __shfl_xor_sync(FULLM, c, 4);
                c += __shfl_xor_sync(FULLM, c, 2);
                c += __shfl_xor_sync(FULLM, c, 1);
                float w = __shfl_xor_sync(FULLM, c, 16);
                float e0 = ex2_hw(hi16 ? w : c);     // exp(compab[n])
                float e1 = ex2_hw(hi16 ? c : w);     // exp(compab[n+1])
                ssum += e0 + e1;
                float2 ig2 = __half22float2(
                    *reinterpret_cast<const __half2*>(ib_ + n));
                wa = fmaf(e0, ig2.x, fmaf(e1, ig2.y, wa));
            }
            const float inv = 1.f / ssum;
            embv[i] = fmaf(wa, inv, fmaf(y0, weY0, fmaf(y1, weY1, bev)));
        }

        // ============ Phase C: GRU (f32 Wih, shared across row pairs) =======
        #pragma unroll
        for (int p = 0; p < 2; p++) {
            ull aR0 = 0ull, aZ0 = 0ull, aN0 = 0ull;
            ull aR1 = 0ull, aZ1 = 0ull, aN1 = 0ull;
            #pragma unroll
            for (int k = 0; k < 16; k++) {
                ull wr = *reinterpret_cast<const ull*>(&sWih[k * 192 + c2]);
                ull wz = *reinterpret_cast<const ull*>(&sWih[k * 192 + 64 + c2]);
                ull wn = *reinterpret_cast<const ull*>(&sWih[k * 192 + 128 + c2]);
                ull e20 = pack2(__shfl_sync(FULLM, embv[2 * p],     k));
                ull e21 = pack2(__shfl_sync(FULLM, embv[2 * p + 1], k));
                asm("fma.rn.f32x2 %0, %1, %2, %0;" : "+l"(aR0) : "l"(e20), "l"(wr));
                asm("fma.rn.f32x2 %0, %1, %2, %0;" : "+l"(aZ0) : "l"(e20), "l"(wz));
                asm("fma.rn.f32x2 %0, %1, %2, %0;" : "+l"(aN0) : "l"(e20), "l"(wn));
                asm("fma.rn.f32x2 %0, %1, %2, %0;" : "+l"(aR1) : "l"(e21), "l"(wr));
                asm("fma.rn.f32x2 %0, %1, %2, %0;" : "+l"(aZ1) : "l"(e21), "l"(wz));
                asm("fma.rn.f32x2 %0, %1, %2, %0;" : "+l"(aN1) : "l"(e21), "l"(wn));
            }
            #pragma unroll
            for (int q = 0; q < 2; q++) {
                const int i  = 2 * p + q;
                const int bl = 4 * wrp + i;
                float2 gR = unpack2(q == 0 ? aR0 : aR1);
                float2 gZ = unpack2(q == 0 ? aZ0 : aZ1);
                float2 gN = unpack2(q == 0 ? aN0 : aN1);
                float2 hR = *reinterpret_cast<const float2*>(&sG[bl * G_STRIDE + 64 + c2]);
                float2 hZ = *reinterpret_cast<const float2*>(&sG[bl * G_STRIDE + 128 + c2]);
                float2 hN = *reinterpret_cast<const float2*>(&sG[bl * G_STRIDE + 192 + c2]);

                float r0 = fmaf(tanh_hw(gR.x + hR.x + cR0), 0.5f, 0.5f);
                float r1 = fmaf(tanh_hw(gR.y + hR.y + cR1), 0.5f, 0.5f);
                float z0 = fmaf(tanh_hw(gZ.x + hZ.x + cZ0), 0.5f, 0.5f);
                float z1 = fmaf(tanh_hw(gZ.y + hZ.y + cZ1), 0.5f, 0.5f);
                float n0 = tanh_hw(gN.x + biN0 + r0 * (hN.x + bhN0));
                float n1 = tanh_hw(gN.y + biN1 + r1 * (hN.y + bhN1));

                float ho0 = shf[bl * 68 + c2];
                float ho1 = shf[bl * 68 + c2 + 1];
                float hn0 = fmaf(z0, ho0 - n0, n0);
                float hn1 = fmaf(z1, ho1 - n1, n1);
                shf[bl * 68 + c2]     = hn0;
                shf[bl * 68 + c2 + 1] = hn1;
                reinterpret_cast<__half2*>(sHh)[bl * 36 + lane] =
                    __floats2half2_rn(hn0, hn1);
            }
        }
        HALF_BAR(1 + grp);   // h (f32+fp16) of this half visible before next mma
    }

    // ---- final output row: ys[pred_len-1] = h @ Wo + bo ----
    #pragma unroll 1
    for (int i = 0; i < 4; i++) {
        const int bl = 4 * wrp + i;
        const int bg = b0 + bl;
        float h0 = shf[bl * 68 + lane];
        float h1 = shf[bl * 68 + 32 + lane];
        float s0 = h0 * wo0 + h1 * wo2;
        float s1 = h0 * wo1 + h1 * wo3;
        float x  = hi16 ? s1 : s0;
        float ys = hi16 ? s0 : s1;
        float v  = x + __shfl_xor_sync(FULLM, ys, 16);
        v += __shfl_xor_sync(FULLM, v, 8);
        v += __shfl_xor_sync(FULLM, v, 4);
        v += __shfl_xor_sync(FULLM, v, 2);
        v += __shfl_xor_sync(FULLM, v, 1);
        float w = __shfl_xor_sync(FULLM, v, 16);
        if (lane == 0) {
            *reinterpret_cast<float2*>(
                &out[((size_t)(pred_len - 1) * B + bg) * 2]) =
                make_float2(v + bo0, w + bo1);
        }
    }
}

// ---------------------------------------------------------------------------
// Host launcher: 2 kernels total.
// ---------------------------------------------------------------------------
extern "C" void kernel_launch(void* const* d_in, const int* in_sizes, int n_in,
                              void* d_out, int out_size)
{
    const int o = (in_sizes[0] == 1) ? 1 : 0;

    const float* lastx = (const float*)d_in[o + 0];
    const float* zo    = (const float*)d_in[o + 1];
    const float* inter = (const float*)d_in[o + 3];
    const float* We    = (const float*)d_in[o + 4];
    const float* be    = (const float*)d_in[o + 5];
    const float* Wih   = (const float*)d_in[o + 6];
    const float* Whh   = (const float*)d_in[o + 7];
    const float* bih   = (const float*)d_in[o + 8];
    const float* bhh   = (const float*)d_in[o + 9];
    const float* Wc1   = (const float*)d_in[o + 10];
    const float* bc1   = (const float*)d_in[o + 11];
    const float* Wc2   = (const float*)d_in[o + 12];
    const float* Wo    = (const float*)d_in[o + 14];
    const float* bo    = (const float*)d_in[o + 15];
    float* out = (float*)d_out;

    const int B = in_sizes[o + 0] / 2;
    const int pred_len = out_size / (2 * B);
    (void)n_in;

    static bool attr_done = false;
    if (!attr_done) {
        cudaFuncSetAttribute(step_kernel,
                             cudaFuncAttributeMaxDynamicSharedMemorySize,
                             SMEM_BYTES);
        attr_done = true;
    }

    precomp_kernel<<<(ND * B) / 64, 128>>>(inter, Wc1, bc1, We, B);

    step_kernel<<<B / BPB, 256, SMEM_BYTES>>>(lastx, zo, Wc1, Whh, bhh,
                                              Wih, bih, Wc2, We, be, Wo, bo,
                                              out, B, pred_len);
}